// round 2
// baseline (speedup 1.0000x reference)
#include <cuda_runtime.h>
#include <cstddef>

// ---------------- Problem constants ----------------
#define NNODES   131072        // B*2*NN
#define HDIM     256
#define EMBD     64
#define NEDGE    1000000
#define NGROUP   2048          // B*2
#define CARD     100

// ---------------- Scratch (no allocs allowed) ----------------
__device__ float g_h0 [NNODES * EMBD];   // embedded features (layer-0 input)
__device__ float g_agg[NNODES * HDIM];   // aggregation buffer (layer0 uses first N*EMBD)
__device__ float g_hA [NNODES * HDIM];   // node features, updated in place per layer

// ---------------- Embedding gather ----------------
// h0[n][e] = table[x[n>>7, n&127] + (n&127)*CARD][e]
__global__ void embed_kernel(const int* __restrict__ x,
                             const float* __restrict__ table,
                             float* __restrict__ h0)
{
    int idx = blockIdx.x * blockDim.x + threadIdx.x;   // over NNODES * (EMBD/4)
    if (idx >= NNODES * (EMBD / 4)) return;
    int n  = idx >> 4;           // EMBD/4 = 16 float4 per node
    int c4 = idx & 15;
    int b   = n >> 7;
    int col = n & 127;
    int row = x[(b << 7) + col] + col * CARD;
    ((float4*)h0)[idx] = ((const float4*)table)[row * (EMBD / 4) + c4];
}

// ---------------- Edge scatter: agg[dst] += hin[src] ----------------
// LOGD4: log2(feature_dim/4). One thread = one float4 chunk of one edge.
template<int LOGD4>
__global__ void scatter_kernel(const int* __restrict__ ei,
                               const float* __restrict__ hin,
                               float* __restrict__ agg)
{
    const int DIV4 = 1 << LOGD4;
    int idx = blockIdx.x * blockDim.x + threadIdx.x;
    if (idx >= NEDGE * DIV4) return;
    int e = idx >> LOGD4;
    int c = idx & (DIV4 - 1);
    int s = __ldg(ei + e);
    int d = __ldg(ei + NEDGE + e);
    float4 v = *(const float4*)(hin + (size_t)s * (DIV4 * 4) + c * 4);
#if defined(__CUDA_ARCH__) && (__CUDA_ARCH__ >= 900)
    atomicAdd((float4*)(agg + (size_t)d * (DIV4 * 4) + c * 4), v);
#else
    float* p = agg + (size_t)d * (DIV4 * 4) + c * 4;
    atomicAdd(p + 0, v.x); atomicAdd(p + 1, v.y);
    atomicAdd(p + 2, v.z); atomicAdd(p + 3, v.w);
#endif
}

// ---------------- Fused GIN layer ----------------
// Block = 256 threads = 8 warps; owns 64 rows x 256 cols.
// Phase 1: acc = ((1+eps)*hin + agg) @ Wa      (K = 64 or 256)
// then bias + LayerNorm(row, warp-shuffle stats) + ReLU -> Ts (smem)
// Phase 2: out = Ts @ Wb + bb   (written in place; block only touches own rows)
// Thread (ty=warp 0..7, tx=lane 0..31) owns rows ty*8+i, cols tx*8+j (8x8 microtile).

__device__ __forceinline__ void load_w_tile(const float* __restrict__ W, int k0,
                                            float* __restrict__ Wsm, int t)
{
#pragma unroll
    for (int j = 0; j < 4; j++) {
        int i4 = t + 256 * j;          // 1024 float4 total
        int r  = i4 >> 6;
        int c4 = i4 & 63;
        *(float4*)(Wsm + r * 256 + c4 * 4) =
            *(const float4*)(W + (k0 + r) * 256 + c4 * 4);
    }
}

__device__ __forceinline__ void mma16(const float* __restrict__ A, int astride,
                                      const float* __restrict__ Wsm,
                                      int ty, int tx, float (&acc)[8][8])
{
#pragma unroll
    for (int kk = 0; kk < 16; kk++) {
        float a[8];
#pragma unroll
        for (int i = 0; i < 8; i++) a[i] = A[(ty * 8 + i) * astride + kk];
        const float4 w0 = *(const float4*)(Wsm + kk * 256 + tx * 8);
        const float4 w1 = *(const float4*)(Wsm + kk * 256 + tx * 8 + 4);
        const float w[8] = {w0.x, w0.y, w0.z, w0.w, w1.x, w1.y, w1.z, w1.w};
#pragma unroll
        for (int i = 0; i < 8; i++)
#pragma unroll
            for (int j = 0; j < 8; j++) acc[i][j] = fmaf(a[i], w[j], acc[i][j]);
    }
}

template<int K>
__global__ void __launch_bounds__(256)
gin_layer_kernel(const float* __restrict__ hin, const float* __restrict__ agg,
                 const float* __restrict__ Wa,  const float* __restrict__ ba,
                 const float* __restrict__ gam, const float* __restrict__ bet,
                 const float* __restrict__ Wb,  const float* __restrict__ bb,
                 const float* __restrict__ epsArr, int layer,
                 float* __restrict__ hout)
{
    extern __shared__ float smem[];
    float* As = smem;                  // 64 x 16
    float* Ws = smem + 1024;           // 16 x 256
    float* Ts = smem + 1024 + 4096;    // 64 x 256

    const int t  = threadIdx.x;
    const int tx = t & 31;
    const int ty = t >> 5;
    const int rowBase = blockIdx.x * 64;
    const float ope = 1.0f + epsArr[layer];

    float acc[8][8];
#pragma unroll
    for (int i = 0; i < 8; i++)
#pragma unroll
        for (int j = 0; j < 8; j++) acc[i][j] = 0.0f;

    // ---- Phase 1: z @ Wa ----
    for (int k0 = 0; k0 < K; k0 += 16) {
        {   // fused z = (1+eps)*hin + agg  -> As tile
            int row = t >> 2;
            int kq  = (t & 3) << 2;
            int gi  = (rowBase + row) * K + k0 + kq;
            float4 hv = *(const float4*)(hin + gi);
            float4 av = *(const float4*)(agg + gi);
            float4 z;
            z.x = fmaf(ope, hv.x, av.x);
            z.y = fmaf(ope, hv.y, av.y);
            z.z = fmaf(ope, hv.z, av.z);
            z.w = fmaf(ope, hv.w, av.w);
            *(float4*)(As + row * 16 + kq) = z;
        }
        load_w_tile(Wa, k0, Ws, t);
        __syncthreads();
        mma16(As, 16, Ws, ty, tx, acc);
        __syncthreads();
    }

    // ---- bias + LayerNorm + ReLU -> Ts ----
    {
        const float4 b0 = *(const float4*)(ba  + tx * 8);
        const float4 b1 = *(const float4*)(ba  + tx * 8 + 4);
        const float4 g0 = *(const float4*)(gam + tx * 8);
        const float4 g1 = *(const float4*)(gam + tx * 8 + 4);
        const float4 e0 = *(const float4*)(bet + tx * 8);
        const float4 e1 = *(const float4*)(bet + tx * 8 + 4);
        const float bv[8] = {b0.x, b0.y, b0.z, b0.w, b1.x, b1.y, b1.z, b1.w};
        const float gv[8] = {g0.x, g0.y, g0.z, g0.w, g1.x, g1.y, g1.z, g1.w};
        const float ev[8] = {e0.x, e0.y, e0.z, e0.w, e1.x, e1.y, e1.z, e1.w};
#pragma unroll
        for (int i = 0; i < 8; i++) {
            float s = 0.0f, s2 = 0.0f;
#pragma unroll
            for (int j = 0; j < 8; j++) {
                float v = acc[i][j] + bv[j];
                acc[i][j] = v;
                s += v;
                s2 = fmaf(v, v, s2);
            }
#pragma unroll
            for (int o = 16; o > 0; o >>= 1) {
                s  += __shfl_xor_sync(0xffffffffu, s,  o);
                s2 += __shfl_xor_sync(0xffffffffu, s2, o);
            }
            float mean = s * (1.0f / 256.0f);
            float var  = s2 * (1.0f / 256.0f) - mean * mean;
            float inv  = rsqrtf(var + 1e-5f);
#pragma unroll
            for (int j = 0; j < 8; j++) {
                float v = (acc[i][j] - mean) * inv;
                v = fmaf(v, gv[j], ev[j]);
                v = fmaxf(v, 0.0f);
                Ts[(ty * 8 + i) * 256 + tx * 8 + j] = v;
            }
        }
    }
    __syncthreads();

    // ---- Phase 2: Ts @ Wb ----
#pragma unroll
    for (int i = 0; i < 8; i++)
#pragma unroll
        for (int j = 0; j < 8; j++) acc[i][j] = 0.0f;

    for (int k0 = 0; k0 < 256; k0 += 16) {
        load_w_tile(Wb, k0, Ws, t);
        __syncthreads();
        mma16(Ts + k0, 256, Ws, ty, tx, acc);
        __syncthreads();
    }

    // ---- bias + store ----
    {
        const float4 b0 = *(const float4*)(bb + tx * 8);
        const float4 b1 = *(const float4*)(bb + tx * 8 + 4);
        const float bv[8] = {b0.x, b0.y, b0.z, b0.w, b1.x, b1.y, b1.z, b1.w};
#pragma unroll
        for (int i = 0; i < 8; i++) {
            int r = rowBase + ty * 8 + i;
            float4 o0, o1;
            o0.x = acc[i][0] + bv[0]; o0.y = acc[i][1] + bv[1];
            o0.z = acc[i][2] + bv[2]; o0.w = acc[i][3] + bv[3];
            o1.x = acc[i][4] + bv[4]; o1.y = acc[i][5] + bv[5];
            o1.z = acc[i][6] + bv[6]; o1.w = acc[i][7] + bv[7];
            *(float4*)(hout + r * 256 + tx * 8)     = o0;
            *(float4*)(hout + r * 256 + tx * 8 + 4) = o1;
        }
    }
}

// ---------------- Final group reduction ----------------
// out[g][f] = sum_{j<64} hA[g*64+j][f]
__global__ void reduce_kernel(const float* __restrict__ h, float* __restrict__ out)
{
    int idx = blockIdx.x * blockDim.x + threadIdx.x;   // over NGROUP * 64 float4
    if (idx >= NGROUP * 64) return;
    int g  = idx >> 6;
    int c4 = idx & 63;
    const float4* p = (const float4*)h + (size_t)g * 64 * 64 + c4;
    float4 s = make_float4(0.f, 0.f, 0.f, 0.f);
#pragma unroll 8
    for (int j = 0; j < 64; j++) {
        float4 v = p[(size_t)j * 64];
        s.x += v.x; s.y += v.y; s.z += v.z; s.w += v.w;
    }
    ((float4*)out)[idx] = s;
}

// ---------------- Launch ----------------
extern "C" void kernel_launch(void* const* d_in, const int* in_sizes, int n_in,
                              void* d_out, int out_size)
{
    const int*   x     = (const int*)  d_in[0];
    const int*   ei    = (const int*)  d_in[1];
    // d_in[2] = los (unused by reference)
    const float* table = (const float*)d_in[3];
    const float* W0a   = (const float*)d_in[4];
    const float* b0a   = (const float*)d_in[5];
    const float* g0    = (const float*)d_in[6];
    const float* be0   = (const float*)d_in[7];
    const float* W0b   = (const float*)d_in[8];
    const float* b0b   = (const float*)d_in[9];
    const float* Wha   = (const float*)d_in[10];
    const float* bha   = (const float*)d_in[11];
    const float* gh    = (const float*)d_in[12];
    const float* beh   = (const float*)d_in[13];
    const float* Whb   = (const float*)d_in[14];
    const float* bhb   = (const float*)d_in[15];
    const float* eps   = (const float*)d_in[16];

    float *h0, *agg, *hA;
    cudaGetSymbolAddress((void**)&h0,  g_h0);
    cudaGetSymbolAddress((void**)&agg, g_agg);
    cudaGetSymbolAddress((void**)&hA,  g_hA);

    const int SMEM_BYTES = (1024 + 4096 + 64 * 256) * (int)sizeof(float); // 86016
    cudaFuncSetAttribute((const void*)gin_layer_kernel<64>,
                         cudaFuncAttributeMaxDynamicSharedMemorySize, SMEM_BYTES);
    cudaFuncSetAttribute((const void*)gin_layer_kernel<256>,
                         cudaFuncAttributeMaxDynamicSharedMemorySize, SMEM_BYTES);

    // Embedding gather
    {
        int total = NNODES * (EMBD / 4);
        embed_kernel<<<(total + 255) / 256, 256>>>(x, table, h0);
    }

    // ---- Layer 0 (K = EMBD = 64) ----
    cudaMemsetAsync(agg, 0, (size_t)NNODES * EMBD * sizeof(float));
    {
        int total = NEDGE * (EMBD / 4);
        scatter_kernel<4><<<(total + 255) / 256, 256>>>(ei, h0, agg);
    }
    gin_layer_kernel<64><<<NNODES / 64, 256, SMEM_BYTES>>>(
        h0, agg, W0a, b0a, g0, be0, W0b, b0b, eps, 0, hA);

    // ---- Layers 1..2 (K = 256), in place ----
    for (int l = 1; l < 3; l++) {
        cudaMemsetAsync(agg, 0, (size_t)NNODES * HDIM * sizeof(float));
        int total = NEDGE * (HDIM / 4);
        scatter_kernel<6><<<(total + 255) / 256, 256>>>(ei, hA, agg);
        gin_layer_kernel<256><<<NNODES / 64, 256, SMEM_BYTES>>>(
            hA, agg, Wha, bha, gh, beh, Whb, bhb, eps, l, hA);
    }

    // ---- Final per-graph-node-group sum ----
    {
        int total = NGROUP * 64;
        reduce_kernel<<<(total + 255) / 256, 256>>>(hA, (float*)d_out);
    }
}

// round 3
// speedup vs baseline: 1.6832x; 1.6832x over previous
#include <cuda_runtime.h>
#include <cstddef>
#include <cstdint>

// ---------------- Problem constants ----------------
#define NNODES   131072        // B*2*NN
#define HDIM     256
#define EMBD     64
#define NEDGE    1000000
#define NGROUP   2048          // B*2
#define CARD     100

// ---------------- Scratch (no allocs allowed) ----------------
__device__ float g_h0 [NNODES * EMBD];   // embedded features (layer-0 input)
__device__ float g_agg[NNODES * HDIM];   // aggregation buffer (layer0 uses first N*EMBD)
__device__ float g_hA [NNODES * HDIM];   // node features, updated in place per layer

// ---------------- Helpers ----------------
__device__ __forceinline__ float tf32r(float x) {
    uint32_t u;
    asm("cvt.rna.tf32.f32 %0, %1;" : "=r"(u) : "f"(x));
    return __uint_as_float(u);
}

__device__ __forceinline__ void mma_tf32(float (&c)[4],
                                         const uint32_t (&a)[4],
                                         const uint32_t (&b)[2]) {
    asm volatile(
        "mma.sync.aligned.m16n8k8.row.col.f32.tf32.tf32.f32 "
        "{%0,%1,%2,%3}, {%4,%5,%6,%7}, {%8,%9}, {%0,%1,%2,%3};"
        : "+f"(c[0]), "+f"(c[1]), "+f"(c[2]), "+f"(c[3])
        : "r"(a[0]), "r"(a[1]), "r"(a[2]), "r"(a[3]),
          "r"(b[0]), "r"(b[1]));
}

// ---------------- Embedding gather ----------------
__global__ void embed_kernel(const int* __restrict__ x,
                             const float* __restrict__ table,
                             float* __restrict__ h0)
{
    int idx = blockIdx.x * blockDim.x + threadIdx.x;   // over NNODES * (EMBD/4)
    if (idx >= NNODES * (EMBD / 4)) return;
    int n  = idx >> 4;           // EMBD/4 = 16 float4 per node
    int c4 = idx & 15;
    int b   = n >> 7;
    int col = n & 127;
    int row = x[(b << 7) + col] + col * CARD;
    ((float4*)h0)[idx] = ((const float4*)table)[row * (EMBD / 4) + c4];
}

// ---------------- Edge scatter: agg[dst] += hin[src] ----------------
template<int LOGD4>
__global__ void scatter_kernel(const int* __restrict__ ei,
                               const float* __restrict__ hin,
                               float* __restrict__ agg)
{
    const int DIV4 = 1 << LOGD4;
    int idx = blockIdx.x * blockDim.x + threadIdx.x;
    if (idx >= NEDGE * DIV4) return;
    int e = idx >> LOGD4;
    int c = idx & (DIV4 - 1);
    int s = __ldg(ei + e);
    int d = __ldg(ei + NEDGE + e);
    float4 v = *(const float4*)(hin + (size_t)s * (DIV4 * 4) + c * 4);
#if defined(__CUDA_ARCH__) && (__CUDA_ARCH__ >= 900)
    atomicAdd((float4*)(agg + (size_t)d * (DIV4 * 4) + c * 4), v);
#else
    float* p = agg + (size_t)d * (DIV4 * 4) + c * 4;
    atomicAdd(p + 0, v.x); atomicAdd(p + 1, v.y);
    atomicAdd(p + 2, v.z); atomicAdd(p + 3, v.w);
#endif
}

// ---------------- Fused GIN layer, tf32 tensor-core version ----------------
// Block = 256 threads = 8 warps; owns 64 rows x 256 cols.
// Warp w owns output columns [w*32, w*32+32): 4 m-tiles (16) x 4 n-tiles (8).
// SMEM strides padded (+4) for conflict-free mma fragment loads.
//
// Phase 1: As = tf32((1+eps)*hin + agg)  [64 x K], Ws = chunk of Wa, mma -> C
// LN:      C(+ba) stored to Ts, row LayerNorm + gamma/beta + ReLU -> tf32 Ts
// Phase 2: Ts @ Wb via mma, + bb, store to global.

template<int K>
__global__ void __launch_bounds__(256)
gin_tc_kernel(const float* __restrict__ hin, const float* __restrict__ agg,
              const float* __restrict__ Wa,  const float* __restrict__ ba,
              const float* __restrict__ gam, const float* __restrict__ bet,
              const float* __restrict__ Wb,  const float* __restrict__ bb,
              const float* __restrict__ epsArr, int layer,
              float* __restrict__ hout)
{
    extern __shared__ float smem[];
    constexpr int ASTR = K + 4;           // padded stride of As
    constexpr int WSTR = 260;             // padded stride of Ws / Ts

    float* Pba = smem;                    // 256
    float* Pg  = smem + 256;              // 256
    float* Pb  = smem + 512;              // 256
    float* As  = smem + 768;              // 64 * ASTR
    float* Ws  = As + 64 * ASTR;          // 64 * 260 (K-chunk of W)
    float* Ts  = Ws + 64 * WSTR;          // 64 * 260

    const int t    = threadIdx.x;
    const int lane = t & 31;
    const int warp = t >> 5;
    const int g    = lane >> 2;           // groupID (0..7)
    const int tg   = lane & 3;            // thread-in-group (0..3)
    const int wb   = warp * 32;           // warp's column base
    const int rowBase = blockIdx.x * 64;
    const float ope = 1.0f + epsArr[layer];

    // params -> smem (for conflict-free scalar LN access)
    Pba[t] = ba[t];  Pg[t] = gam[t];  Pb[t] = bet[t];

    // ---- Stage As: z = (1+eps)*hin + agg, rounded to tf32 ----
    {
        constexpr int NF4 = (64 * K) / 4 / 256;   // 4 (K=64) or 16 (K=256)
#pragma unroll
        for (int j = 0; j < NF4; j++) {
            int i4  = t + 256 * j;
            int row = i4 / (K / 4);
            int c4  = i4 % (K / 4);
            const float* hp = hin + (size_t)(rowBase + row) * K + c4 * 4;
            const float* ap = agg + (size_t)(rowBase + row) * K + c4 * 4;
            float4 hv = *(const float4*)hp;
            float4 av = *(const float4*)ap;
            float4 z;
            z.x = tf32r(fmaf(ope, hv.x, av.x));
            z.y = tf32r(fmaf(ope, hv.y, av.y));
            z.z = tf32r(fmaf(ope, hv.z, av.z));
            z.w = tf32r(fmaf(ope, hv.w, av.w));
            *(float4*)(As + row * ASTR + c4 * 4) = z;
        }
    }

    float C[4][4][4];                     // [mt][nt][frag]
#pragma unroll
    for (int mt = 0; mt < 4; mt++)
#pragma unroll
        for (int nt = 0; nt < 4; nt++)
#pragma unroll
            for (int q = 0; q < 4; q++) C[mt][nt][q] = 0.0f;

    // ---- Phase 1: As @ Wa ----
    for (int cc = 0; cc < K; cc += 64) {
#pragma unroll
        for (int j = 0; j < 16; j++) {    // load 64x256 W chunk, tf32-rounded
            int i4 = t + 256 * j;
            int r  = i4 >> 6;
            int c4 = i4 & 63;
            float4 w = *(const float4*)(Wa + (size_t)(cc + r) * 256 + c4 * 4);
            w.x = tf32r(w.x); w.y = tf32r(w.y); w.z = tf32r(w.z); w.w = tf32r(w.w);
            *(float4*)(Ws + r * WSTR + c4 * 4) = w;
        }
        __syncthreads();

#pragma unroll
        for (int kk = 0; kk < 64; kk += 8) {
            uint32_t Bf[4][2];
#pragma unroll
            for (int nt = 0; nt < 4; nt++) {
                int col = wb + nt * 8 + g;
                Bf[nt][0] = __float_as_uint(Ws[(kk + tg)     * WSTR + col]);
                Bf[nt][1] = __float_as_uint(Ws[(kk + tg + 4) * WSTR + col]);
            }
            const int kgl = cc + kk;
#pragma unroll
            for (int mt = 0; mt < 4; mt++) {
                int r0 = mt * 16 + g;
                uint32_t Af[4];
                Af[0] = __float_as_uint(As[ r0      * ASTR + kgl + tg]);
                Af[1] = __float_as_uint(As[(r0 + 8) * ASTR + kgl + tg]);
                Af[2] = __float_as_uint(As[ r0      * ASTR + kgl + tg + 4]);
                Af[3] = __float_as_uint(As[(r0 + 8) * ASTR + kgl + tg + 4]);
#pragma unroll
                for (int nt = 0; nt < 4; nt++) mma_tf32(C[mt][nt], Af, Bf[nt]);
            }
        }
        __syncthreads();
    }

    // ---- store C frags to Ts ----
#pragma unroll
    for (int mt = 0; mt < 4; mt++)
#pragma unroll
        for (int nt = 0; nt < 4; nt++) {
            int r0  = mt * 16 + g;
            int col = wb + nt * 8 + 2 * tg;
            *(float2*)(Ts +  r0      * WSTR + col) = make_float2(C[mt][nt][0], C[mt][nt][1]);
            *(float2*)(Ts + (r0 + 8) * WSTR + col) = make_float2(C[mt][nt][2], C[mt][nt][3]);
        }
    __syncthreads();

    // ---- bias + LayerNorm + ReLU (in Ts), output rounded to tf32 ----
    {
        int row = t >> 2;
        int q   = t & 3;
        float s = 0.0f, s2 = 0.0f;
#pragma unroll
        for (int c = 0; c < 64; c++) {
            int col = q + c * 4;
            float v = Ts[row * WSTR + col] + Pba[col];
            s += v;
            s2 = fmaf(v, v, s2);
        }
        s  += __shfl_xor_sync(0xffffffffu, s, 1);
        s  += __shfl_xor_sync(0xffffffffu, s, 2);
        s2 += __shfl_xor_sync(0xffffffffu, s2, 1);
        s2 += __shfl_xor_sync(0xffffffffu, s2, 2);
        float mean = s * (1.0f / 256.0f);
        float var  = s2 * (1.0f / 256.0f) - mean * mean;
        float inv  = rsqrtf(var + 1e-5f);
#pragma unroll
        for (int c = 0; c < 64; c++) {
            int col = q + c * 4;
            float v = (Ts[row * WSTR + col] + Pba[col] - mean) * inv;
            v = fmaf(v, Pg[col], Pb[col]);
            v = fmaxf(v, 0.0f);
            Ts[row * WSTR + col] = tf32r(v);
        }
    }
    __syncthreads();

    // ---- Phase 2: Ts @ Wb ----
#pragma unroll
    for (int mt = 0; mt < 4; mt++)
#pragma unroll
        for (int nt = 0; nt < 4; nt++)
#pragma unroll
            for (int q = 0; q < 4; q++) C[mt][nt][q] = 0.0f;

    for (int cc = 0; cc < 256; cc += 64) {
#pragma unroll
        for (int j = 0; j < 16; j++) {
            int i4 = t + 256 * j;
            int r  = i4 >> 6;
            int c4 = i4 & 63;
            float4 w = *(const float4*)(Wb + (size_t)(cc + r) * 256 + c4 * 4);
            w.x = tf32r(w.x); w.y = tf32r(w.y); w.z = tf32r(w.z); w.w = tf32r(w.w);
            *(float4*)(Ws + r * WSTR + c4 * 4) = w;
        }
        __syncthreads();

#pragma unroll
        for (int kk = 0; kk < 64; kk += 8) {
            uint32_t Bf[4][2];
#pragma unroll
            for (int nt = 0; nt < 4; nt++) {
                int col = wb + nt * 8 + g;
                Bf[nt][0] = __float_as_uint(Ws[(kk + tg)     * WSTR + col]);
                Bf[nt][1] = __float_as_uint(Ws[(kk + tg + 4) * WSTR + col]);
            }
            const int kgl = cc + kk;
#pragma unroll
            for (int mt = 0; mt < 4; mt++) {
                int r0 = mt * 16 + g;
                uint32_t Af[4];
                Af[0] = __float_as_uint(Ts[ r0      * WSTR + kgl + tg]);
                Af[1] = __float_as_uint(Ts[(r0 + 8) * WSTR + kgl + tg]);
                Af[2] = __float_as_uint(Ts[ r0      * WSTR + kgl + tg + 4]);
                Af[3] = __float_as_uint(Ts[(r0 + 8) * WSTR + kgl + tg + 4]);
#pragma unroll
                for (int nt = 0; nt < 4; nt++) mma_tf32(C[mt][nt], Af, Bf[nt]);
            }
        }
        __syncthreads();
    }

    // ---- + bb, store to global ----
#pragma unroll
    for (int mt = 0; mt < 4; mt++)
#pragma unroll
        for (int nt = 0; nt < 4; nt++) {
            int r0  = rowBase + mt * 16 + g;
            int col = wb + nt * 8 + 2 * tg;
            float2 bbv = *(const float2*)(bb + col);
            float2 o0 = make_float2(C[mt][nt][0] + bbv.x, C[mt][nt][1] + bbv.y);
            float2 o1 = make_float2(C[mt][nt][2] + bbv.x, C[mt][nt][3] + bbv.y);
            *(float2*)(hout + (size_t) r0      * 256 + col) = o0;
            *(float2*)(hout + (size_t)(r0 + 8) * 256 + col) = o1;
        }
}

// ---------------- Final group reduction ----------------
__global__ void reduce_kernel(const float* __restrict__ h, float* __restrict__ out)
{
    int idx = blockIdx.x * blockDim.x + threadIdx.x;   // over NGROUP * 64 float4
    if (idx >= NGROUP * 64) return;
    int g  = idx >> 6;
    int c4 = idx & 63;
    const float4* p = (const float4*)h + (size_t)g * 64 * 64 + c4;
    float4 s = make_float4(0.f, 0.f, 0.f, 0.f);
#pragma unroll 8
    for (int j = 0; j < 64; j++) {
        float4 v = p[(size_t)j * 64];
        s.x += v.x; s.y += v.y; s.z += v.z; s.w += v.w;
    }
    ((float4*)out)[idx] = s;
}

// ---------------- Launch ----------------
extern "C" void kernel_launch(void* const* d_in, const int* in_sizes, int n_in,
                              void* d_out, int out_size)
{
    const int*   x     = (const int*)  d_in[0];
    const int*   ei    = (const int*)  d_in[1];
    // d_in[2] = los (unused by reference)
    const float* table = (const float*)d_in[3];
    const float* W0a   = (const float*)d_in[4];
    const float* b0a   = (const float*)d_in[5];
    const float* g0    = (const float*)d_in[6];
    const float* be0   = (const float*)d_in[7];
    const float* W0b   = (const float*)d_in[8];
    const float* b0b   = (const float*)d_in[9];
    const float* Wha   = (const float*)d_in[10];
    const float* bha   = (const float*)d_in[11];
    const float* gh    = (const float*)d_in[12];
    const float* beh   = (const float*)d_in[13];
    const float* Whb   = (const float*)d_in[14];
    const float* bhb   = (const float*)d_in[15];
    const float* eps   = (const float*)d_in[16];

    float *h0, *agg, *hA;
    cudaGetSymbolAddress((void**)&h0,  g_h0);
    cudaGetSymbolAddress((void**)&agg, g_agg);
    cudaGetSymbolAddress((void**)&hA,  g_hA);

    const int SMEM64  = (768 + 64 * 68  + 64 * 260 * 2) * (int)sizeof(float); // 153600
    const int SMEM256 = (768 + 64 * 260 + 64 * 260 * 2) * (int)sizeof(float); // 202752
    cudaFuncSetAttribute((const void*)gin_tc_kernel<64>,
                         cudaFuncAttributeMaxDynamicSharedMemorySize, SMEM64);
    cudaFuncSetAttribute((const void*)gin_tc_kernel<256>,
                         cudaFuncAttributeMaxDynamicSharedMemorySize, SMEM256);

    // Embedding gather
    {
        int total = NNODES * (EMBD / 4);
        embed_kernel<<<(total + 255) / 256, 256>>>(x, table, h0);
    }

    // ---- Layer 0 (K = EMBD = 64) ----
    cudaMemsetAsync(agg, 0, (size_t)NNODES * EMBD * sizeof(float));
    {
        int total = NEDGE * (EMBD / 4);
        scatter_kernel<4><<<(total + 255) / 256, 256>>>(ei, h0, agg);
    }
    gin_tc_kernel<64><<<NNODES / 64, 256, SMEM64>>>(
        h0, agg, W0a, b0a, g0, be0, W0b, b0b, eps, 0, hA);

    // ---- Layers 1..2 (K = 256), in place ----
    for (int l = 1; l < 3; l++) {
        cudaMemsetAsync(agg, 0, (size_t)NNODES * HDIM * sizeof(float));
        int total = NEDGE * (HDIM / 4);
        scatter_kernel<6><<<(total + 255) / 256, 256>>>(ei, hA, agg);
        gin_tc_kernel<256><<<NNODES / 64, 256, SMEM256>>>(
            hA, agg, Wha, bha, gh, beh, Whb, bhb, eps, l, hA);
    }

    // ---- Final per-graph-node-group sum ----
    {
        int total = NGROUP * 64;
        reduce_kernel<<<(total + 255) / 256, 256>>>(hA, (float*)d_out);
    }
}

// round 4
// speedup vs baseline: 1.8950x; 1.1258x over previous
#include <cuda_runtime.h>
#include <cstddef>
#include <cstdint>

// ---------------- Problem constants ----------------
#define NNODES   131072        // B*2*NN
#define HDIM     256
#define EMBD     64
#define NEDGE    1000000
#define NGROUP   2048          // B*2
#define CARD     100

// ---------------- Scratch (no allocs allowed) ----------------
__device__ float g_h0 [NNODES * EMBD];   // embedded features (layer-0 input)
__device__ float g_agg[NNODES * HDIM];   // aggregation buffer
__device__ float g_hA [NNODES * HDIM];   // node features, updated in place per layer
__device__ int   g_deg[NNODES + 1];      // degree histogram
__device__ int   g_off[NNODES + 1];      // CSR row offsets
__device__ int   g_cur[NNODES];          // fill cursors
__device__ int   g_srcl[NEDGE];          // CSR: src ids grouped by dst

// ---------------- Helpers ----------------
__device__ __forceinline__ float tf32r(float x) {
    uint32_t u;
    asm("cvt.rna.tf32.f32 %0, %1;" : "=r"(u) : "f"(x));
    return __uint_as_float(u);
}

__device__ __forceinline__ void mma_tf32(float (&c)[4],
                                         const uint32_t (&a)[4],
                                         const uint32_t (&b)[2]) {
    asm volatile(
        "mma.sync.aligned.m16n8k8.row.col.f32.tf32.tf32.f32 "
        "{%0,%1,%2,%3}, {%4,%5,%6,%7}, {%8,%9}, {%0,%1,%2,%3};"
        : "+f"(c[0]), "+f"(c[1]), "+f"(c[2]), "+f"(c[3])
        : "r"(a[0]), "r"(a[1]), "r"(a[2]), "r"(a[3]),
          "r"(b[0]), "r"(b[1]));
}

// ---------------- Embedding gather ----------------
__global__ void embed_kernel(const int* __restrict__ x,
                             const float* __restrict__ table,
                             float* __restrict__ h0)
{
    int idx = blockIdx.x * blockDim.x + threadIdx.x;
    if (idx >= NNODES * (EMBD / 4)) return;
    int n  = idx >> 4;
    int c4 = idx & 15;
    int b   = n >> 7;
    int col = n & 127;
    int row = x[(b << 7) + col] + col * CARD;
    ((float4*)h0)[idx] = ((const float4*)table)[row * (EMBD / 4) + c4];
}

// ---------------- CSR build ----------------
__global__ void hist_kernel(const int* __restrict__ ei, int* __restrict__ deg)
{
    int e = blockIdx.x * blockDim.x + threadIdx.x;
    if (e < NEDGE) atomicAdd(deg + ei[NEDGE + e], 1);
}

// single block, 1024 threads; 131072 = 1024 * 128
__global__ void scan_kernel(const int* __restrict__ deg,
                            int* __restrict__ off, int* __restrict__ cur)
{
    __shared__ int ps[1024];
    const int t = threadIdx.x;
    const int base = t * 128;
    int s = 0;
#pragma unroll 8
    for (int i = 0; i < 128; i++) s += deg[base + i];
    ps[t] = s;
    __syncthreads();
    // Hillis-Steele inclusive scan
    for (int o = 1; o < 1024; o <<= 1) {
        int v = (t >= o) ? ps[t - o] : 0;
        __syncthreads();
        ps[t] += v;
        __syncthreads();
    }
    int run = ps[t] - s;   // exclusive prefix for this thread's range
#pragma unroll 8
    for (int i = 0; i < 128; i++) {
        int d = deg[base + i];
        off[base + i] = run;
        cur[base + i] = run;
        run += d;
    }
    if (t == 1023) off[NNODES] = run;
}

__global__ void fill_kernel(const int* __restrict__ ei,
                            int* __restrict__ cur, int* __restrict__ srcl)
{
    int e = blockIdx.x * blockDim.x + threadIdx.x;
    if (e >= NEDGE) return;
    int d = ei[NEDGE + e];
    int pos = atomicAdd(cur + d, 1);
    srcl[pos] = ei[e];
}

// ---------------- CSR aggregate: agg[n] = sum_{s in nbr(n)} hin[s] ----------------
template<int D>
__global__ void gather_agg_kernel(const int* __restrict__ off,
                                  const int* __restrict__ srcl,
                                  const float* __restrict__ hin,
                                  float* __restrict__ agg)
{
    constexpr int TPN   = (D / 4 < 32) ? D / 4 : 32;   // threads per node
    constexpr int CHUNK = (D / 4) / TPN;               // float4 per thread
    int gid  = blockIdx.x * blockDim.x + threadIdx.x;
    int node = gid / TPN;
    int sub  = gid % TPN;
    if (node >= NNODES) return;
    int beg = off[node], end = off[node + 1];
    float4 acc[CHUNK];
#pragma unroll
    for (int c = 0; c < CHUNK; c++) acc[c] = make_float4(0.f, 0.f, 0.f, 0.f);
    for (int p = beg; p < end; p++) {
        const float4* r = (const float4*)(hin + (size_t)__ldg(srcl + p) * D);
#pragma unroll
        for (int c = 0; c < CHUNK; c++) {
            float4 v = __ldg(r + sub + c * TPN);
            acc[c].x += v.x; acc[c].y += v.y;
            acc[c].z += v.z; acc[c].w += v.w;
        }
    }
    float4* o = (float4*)(agg + (size_t)node * D);
#pragma unroll
    for (int c = 0; c < CHUNK; c++) o[sub + c * TPN] = acc[c];
}

// ---------------- Fused GIN layer, tf32 tensor cores, 512 threads ----------------
// Block = 512 threads = 16 warps; owns 64 rows x 256 cols.
// Warp w owns output columns [w*16, w*16+16): 4 m-tiles (16) x 2 n-tiles (8).

template<int K>
__global__ void __launch_bounds__(512)
gin_tc_kernel(const float* __restrict__ hin, const float* __restrict__ agg,
              const float* __restrict__ Wa,  const float* __restrict__ ba,
              const float* __restrict__ gam, const float* __restrict__ bet,
              const float* __restrict__ Wb,  const float* __restrict__ bb,
              const float* __restrict__ epsArr, int layer,
              float* __restrict__ hout)
{
    extern __shared__ float smem[];
    constexpr int ASTR = K + 4;
    constexpr int WSTR = 260;

    float* Pba = smem;                    // 256
    float* Pg  = smem + 256;              // 256
    float* Pb  = smem + 512;              // 256
    float* As  = smem + 768;              // 64 * ASTR
    float* Ws  = As + 64 * ASTR;          // 64 * 260
    float* Ts  = Ws + 64 * WSTR;          // 64 * 260

    const int t    = threadIdx.x;
    const int lane = t & 31;
    const int warp = t >> 5;              // 0..15
    const int g    = lane >> 2;
    const int tg   = lane & 3;
    const int wb   = warp * 16;           // warp column base
    const int rowBase = blockIdx.x * 64;
    const float ope = 1.0f + epsArr[layer];

    if (t < 256) { Pba[t] = ba[t];  Pg[t] = gam[t];  Pb[t] = bet[t]; }

    // ---- Stage As: z = (1+eps)*hin + agg, rounded to tf32 ----
    {
        constexpr int NF4 = (64 * K) / 4 / 512;   // 2 (K=64) or 8 (K=256)
#pragma unroll
        for (int j = 0; j < NF4; j++) {
            int i4  = t + 512 * j;
            int row = i4 / (K / 4);
            int c4  = i4 % (K / 4);
            const float* hp = hin + (size_t)(rowBase + row) * K + c4 * 4;
            const float* ap = agg + (size_t)(rowBase + row) * K + c4 * 4;
            float4 hv = *(const float4*)hp;
            float4 av = *(const float4*)ap;
            float4 z;
            z.x = tf32r(fmaf(ope, hv.x, av.x));
            z.y = tf32r(fmaf(ope, hv.y, av.y));
            z.z = tf32r(fmaf(ope, hv.z, av.z));
            z.w = tf32r(fmaf(ope, hv.w, av.w));
            *(float4*)(As + row * ASTR + c4 * 4) = z;
        }
    }

    float C[4][2][4];
#pragma unroll
    for (int mt = 0; mt < 4; mt++)
#pragma unroll
        for (int nt = 0; nt < 2; nt++)
#pragma unroll
            for (int q = 0; q < 4; q++) C[mt][nt][q] = 0.0f;

    // ---- Phase 1: As @ Wa ----
    for (int cc = 0; cc < K; cc += 64) {
#pragma unroll
        for (int j = 0; j < 8; j++) {     // 64x256 W chunk
            int i4 = t + 512 * j;
            int r  = i4 >> 6;
            int c4 = i4 & 63;
            float4 w = *(const float4*)(Wa + (size_t)(cc + r) * 256 + c4 * 4);
            w.x = tf32r(w.x); w.y = tf32r(w.y); w.z = tf32r(w.z); w.w = tf32r(w.w);
            *(float4*)(Ws + r * WSTR + c4 * 4) = w;
        }
        __syncthreads();

#pragma unroll
        for (int kk = 0; kk < 64; kk += 8) {
            uint32_t Bf[2][2];
#pragma unroll
            for (int nt = 0; nt < 2; nt++) {
                int col = wb + nt * 8 + g;
                Bf[nt][0] = __float_as_uint(Ws[(kk + tg)     * WSTR + col]);
                Bf[nt][1] = __float_as_uint(Ws[(kk + tg + 4) * WSTR + col]);
            }
            const int kgl = cc + kk;
#pragma unroll
            for (int mt = 0; mt < 4; mt++) {
                int r0 = mt * 16 + g;
                uint32_t Af[4];
                Af[0] = __float_as_uint(As[ r0      * ASTR + kgl + tg]);
                Af[1] = __float_as_uint(As[(r0 + 8) * ASTR + kgl + tg]);
                Af[2] = __float_as_uint(As[ r0      * ASTR + kgl + tg + 4]);
                Af[3] = __float_as_uint(As[(r0 + 8) * ASTR + kgl + tg + 4]);
#pragma unroll
                for (int nt = 0; nt < 2; nt++) mma_tf32(C[mt][nt], Af, Bf[nt]);
            }
        }
        __syncthreads();
    }

    // ---- store C frags to Ts ----
#pragma unroll
    for (int mt = 0; mt < 4; mt++)
#pragma unroll
        for (int nt = 0; nt < 2; nt++) {
            int r0  = mt * 16 + g;
            int col = wb + nt * 8 + 2 * tg;
            *(float2*)(Ts +  r0      * WSTR + col) = make_float2(C[mt][nt][0], C[mt][nt][1]);
            *(float2*)(Ts + (r0 + 8) * WSTR + col) = make_float2(C[mt][nt][2], C[mt][nt][3]);
        }
    __syncthreads();

    // ---- bias + LayerNorm + ReLU (in Ts), tf32-rounded ----
    if (t < 256) {
        int row = t >> 2;
        int q   = t & 3;
        float s = 0.0f, s2 = 0.0f;
#pragma unroll
        for (int c = 0; c < 64; c++) {
            int col = q + c * 4;
            float v = Ts[row * WSTR + col] + Pba[col];
            s += v;
            s2 = fmaf(v, v, s2);
        }
        s  += __shfl_xor_sync(0xffffffffu, s, 1);
        s  += __shfl_xor_sync(0xffffffffu, s, 2);
        s2 += __shfl_xor_sync(0xffffffffu, s2, 1);
        s2 += __shfl_xor_sync(0xffffffffu, s2, 2);
        float mean = s * (1.0f / 256.0f);
        float var  = s2 * (1.0f / 256.0f) - mean * mean;
        float inv  = rsqrtf(var + 1e-5f);
#pragma unroll
        for (int c = 0; c < 64; c++) {
            int col = q + c * 4;
            float v = (Ts[row * WSTR + col] + Pba[col] - mean) * inv;
            v = fmaf(v, Pg[col], Pb[col]);
            v = fmaxf(v, 0.0f);
            Ts[row * WSTR + col] = tf32r(v);
        }
    }
    __syncthreads();

    // ---- Phase 2: Ts @ Wb ----
#pragma unroll
    for (int mt = 0; mt < 4; mt++)
#pragma unroll
        for (int nt = 0; nt < 2; nt++)
#pragma unroll
            for (int q = 0; q < 4; q++) C[mt][nt][q] = 0.0f;

    for (int cc = 0; cc < 256; cc += 64) {
#pragma unroll
        for (int j = 0; j < 8; j++) {
            int i4 = t + 512 * j;
            int r  = i4 >> 6;
            int c4 = i4 & 63;
            float4 w = *(const float4*)(Wb + (size_t)(cc + r) * 256 + c4 * 4);
            w.x = tf32r(w.x); w.y = tf32r(w.y); w.z = tf32r(w.z); w.w = tf32r(w.w);
            *(float4*)(Ws + r * WSTR + c4 * 4) = w;
        }
        __syncthreads();

#pragma unroll
        for (int kk = 0; kk < 64; kk += 8) {
            uint32_t Bf[2][2];
#pragma unroll
            for (int nt = 0; nt < 2; nt++) {
                int col = wb + nt * 8 + g;
                Bf[nt][0] = __float_as_uint(Ws[(kk + tg)     * WSTR + col]);
                Bf[nt][1] = __float_as_uint(Ws[(kk + tg + 4) * WSTR + col]);
            }
            const int kgl = cc + kk;
#pragma unroll
            for (int mt = 0; mt < 4; mt++) {
                int r0 = mt * 16 + g;
                uint32_t Af[4];
                Af[0] = __float_as_uint(Ts[ r0      * WSTR + kgl + tg]);
                Af[1] = __float_as_uint(Ts[(r0 + 8) * WSTR + kgl + tg]);
                Af[2] = __float_as_uint(Ts[ r0      * WSTR + kgl + tg + 4]);
                Af[3] = __float_as_uint(Ts[(r0 + 8) * WSTR + kgl + tg + 4]);
#pragma unroll
                for (int nt = 0; nt < 2; nt++) mma_tf32(C[mt][nt], Af, Bf[nt]);
            }
        }
        __syncthreads();
    }

    // ---- + bb, store to global ----
#pragma unroll
    for (int mt = 0; mt < 4; mt++)
#pragma unroll
        for (int nt = 0; nt < 2; nt++) {
            int r0  = rowBase + mt * 16 + g;
            int col = wb + nt * 8 + 2 * tg;
            float2 bbv = *(const float2*)(bb + col);
            float2 o0 = make_float2(C[mt][nt][0] + bbv.x, C[mt][nt][1] + bbv.y);
            float2 o1 = make_float2(C[mt][nt][2] + bbv.x, C[mt][nt][3] + bbv.y);
            *(float2*)(hout + (size_t) r0      * 256 + col) = o0;
            *(float2*)(hout + (size_t)(r0 + 8) * 256 + col) = o1;
        }
}

// ---------------- Final group reduction ----------------
__global__ void reduce_kernel(const float* __restrict__ h, float* __restrict__ out)
{
    int idx = blockIdx.x * blockDim.x + threadIdx.x;
    if (idx >= NGROUP * 64) return;
    int g  = idx >> 6;
    int c4 = idx & 63;
    const float4* p = (const float4*)h + (size_t)g * 64 * 64 + c4;
    float4 s = make_float4(0.f, 0.f, 0.f, 0.f);
#pragma unroll 8
    for (int j = 0; j < 64; j++) {
        float4 v = p[(size_t)j * 64];
        s.x += v.x; s.y += v.y; s.z += v.z; s.w += v.w;
    }
    ((float4*)out)[idx] = s;
}

// ---------------- Launch ----------------
extern "C" void kernel_launch(void* const* d_in, const int* in_sizes, int n_in,
                              void* d_out, int out_size)
{
    const int*   x     = (const int*)  d_in[0];
    const int*   ei    = (const int*)  d_in[1];
    // d_in[2] = los (unused by reference)
    const float* table = (const float*)d_in[3];
    const float* W0a   = (const float*)d_in[4];
    const float* b0a   = (const float*)d_in[5];
    const float* g0    = (const float*)d_in[6];
    const float* be0   = (const float*)d_in[7];
    const float* W0b   = (const float*)d_in[8];
    const float* b0b   = (const float*)d_in[9];
    const float* Wha   = (const float*)d_in[10];
    const float* bha   = (const float*)d_in[11];
    const float* gh    = (const float*)d_in[12];
    const float* beh   = (const float*)d_in[13];
    const float* Whb   = (const float*)d_in[14];
    const float* bhb   = (const float*)d_in[15];
    const float* eps   = (const float*)d_in[16];

    float *h0, *agg, *hA;
    int *deg, *off, *cur, *srcl;
    cudaGetSymbolAddress((void**)&h0,   g_h0);
    cudaGetSymbolAddress((void**)&agg,  g_agg);
    cudaGetSymbolAddress((void**)&hA,   g_hA);
    cudaGetSymbolAddress((void**)&deg,  g_deg);
    cudaGetSymbolAddress((void**)&off,  g_off);
    cudaGetSymbolAddress((void**)&cur,  g_cur);
    cudaGetSymbolAddress((void**)&srcl, g_srcl);

    const int SMEM64  = (768 + 64 * 68  + 64 * 260 * 2) * (int)sizeof(float);
    const int SMEM256 = (768 + 64 * 260 + 64 * 260 * 2) * (int)sizeof(float);
    cudaFuncSetAttribute((const void*)gin_tc_kernel<64>,
                         cudaFuncAttributeMaxDynamicSharedMemorySize, SMEM64);
    cudaFuncSetAttribute((const void*)gin_tc_kernel<256>,
                         cudaFuncAttributeMaxDynamicSharedMemorySize, SMEM256);

    // ---- CSR build (reused by all 3 layers) ----
    cudaMemsetAsync(deg, 0, (NNODES + 1) * sizeof(int));
    hist_kernel<<<(NEDGE + 255) / 256, 256>>>(ei, deg);
    scan_kernel<<<1, 1024>>>(deg, off, cur);
    fill_kernel<<<(NEDGE + 255) / 256, 256>>>(ei, cur, srcl);

    // ---- Embedding gather ----
    {
        int total = NNODES * (EMBD / 4);
        embed_kernel<<<(total + 255) / 256, 256>>>(x, table, h0);
    }

    // ---- Layer 0 (K = EMBD = 64) ----
    {
        int total = NNODES * 16;    // TPN=16
        gather_agg_kernel<64><<<(total + 255) / 256, 256>>>(off, srcl, h0, agg);
    }
    gin_tc_kernel<64><<<NNODES / 64, 512, SMEM64>>>(
        h0, agg, W0a, b0a, g0, be0, W0b, b0b, eps, 0, hA);

    // ---- Layers 1..2 (K = 256), in place ----
    for (int l = 1; l < 3; l++) {
        int total = NNODES * 32;    // TPN=32
        gather_agg_kernel<256><<<(total + 255) / 256, 256>>>(off, srcl, hA, agg);
        gin_tc_kernel<256><<<NNODES / 64, 512, SMEM256>>>(
            hA, agg, Wha, bha, gh, beh, Whb, bhb, eps, l, hA);
    }

    // ---- Final per-graph-node-group sum ----
    {
        int total = NGROUP * 64;
        reduce_kernel<<<(total + 255) / 256, 256>>>(hA, (float*)d_out);
    }
}

// round 5
// speedup vs baseline: 2.3143x; 1.2213x over previous
#include <cuda_runtime.h>
#include <cstddef>
#include <cstdint>

// ---------------- Problem constants ----------------
#define NNODES   131072        // B*2*NN
#define HDIM     256
#define EMBD     64
#define NEDGE    1000000
#define NGROUP   2048          // B*2
#define CARD     100

// ---------------- Scratch (no allocs allowed) ----------------
__device__ float g_h0 [NNODES * EMBD];
__device__ float g_agg[NNODES * HDIM];
__device__ float g_hA [NNODES * HDIM];
__device__ int   g_deg[NNODES + 1];
__device__ int   g_off[NNODES + 1];
__device__ int   g_cur[NNODES];
__device__ int   g_srcl[NEDGE];
// fragment-ordered tf32 weights: W0a(8 k8) | W0b(32) | Wha(32) | Whb(32), each k8 block = 256 cols * 4 tg float2
__device__ float2 g_wf[(8 + 32 + 32 + 32) * 1024];

// ---------------- Helpers ----------------
__device__ __forceinline__ float tf32r(float x) {
    uint32_t u;
    asm("cvt.rna.tf32.f32 %0, %1;" : "=r"(u) : "f"(x));
    return __uint_as_float(u);
}

__device__ __forceinline__ void mma_tf32(float (&c)[4],
                                         const uint32_t (&a)[4],
                                         const uint32_t (&b)[2]) {
    asm volatile(
        "mma.sync.aligned.m16n8k8.row.col.f32.tf32.tf32.f32 "
        "{%0,%1,%2,%3}, {%4,%5,%6,%7}, {%8,%9}, {%0,%1,%2,%3};"
        : "+f"(c[0]), "+f"(c[1]), "+f"(c[2]), "+f"(c[3])
        : "r"(a[0]), "r"(a[1]), "r"(a[2]), "r"(a[3]),
          "r"(b[0]), "r"(b[1]));
}

// ---------------- Weight pre-convert to fragment order ----------------
// Wf[(k8*256 + col)*4 + tg] = { tf32(W[k8*8+tg][col]), tf32(W[k8*8+tg+4][col]) }
__global__ void wcvt_kernel(const float* __restrict__ W, float2* __restrict__ Wf,
                            int k8count)
{
    int idx = blockIdx.x * blockDim.x + threadIdx.x;
    if (idx >= k8count * 1024) return;
    int tg  = idx & 3;
    int col = (idx >> 2) & 255;
    int k8  = idx >> 10;
    float lo = W[(k8 * 8 + tg)     * 256 + col];
    float hi = W[(k8 * 8 + tg + 4) * 256 + col];
    Wf[idx] = make_float2(tf32r(lo), tf32r(hi));
}

// ---------------- Embedding gather ----------------
__global__ void embed_kernel(const int* __restrict__ x,
                             const float* __restrict__ table,
                             float* __restrict__ h0)
{
    int idx = blockIdx.x * blockDim.x + threadIdx.x;
    if (idx >= NNODES * (EMBD / 4)) return;
    int n  = idx >> 4;
    int c4 = idx & 15;
    int b   = n >> 7;
    int col = n & 127;
    int row = x[(b << 7) + col] + col * CARD;
    ((float4*)h0)[idx] = ((const float4*)table)[row * (EMBD / 4) + c4];
}

// ---------------- CSR build ----------------
__global__ void hist_kernel(const int* __restrict__ ei, int* __restrict__ deg)
{
    int e = blockIdx.x * blockDim.x + threadIdx.x;
    if (e < NEDGE) atomicAdd(deg + ei[NEDGE + e], 1);
}

__global__ void scan_kernel(const int* __restrict__ deg,
                            int* __restrict__ off, int* __restrict__ cur)
{
    __shared__ int ps[1024];
    const int t = threadIdx.x;
    const int base = t * 128;
    int s = 0;
#pragma unroll 8
    for (int i = 0; i < 128; i++) s += deg[base + i];
    ps[t] = s;
    __syncthreads();
    for (int o = 1; o < 1024; o <<= 1) {
        int v = (t >= o) ? ps[t - o] : 0;
        __syncthreads();
        ps[t] += v;
        __syncthreads();
    }
    int run = ps[t] - s;
#pragma unroll 8
    for (int i = 0; i < 128; i++) {
        int d = deg[base + i];
        off[base + i] = run;
        cur[base + i] = run;
        run += d;
    }
    if (t == 1023) off[NNODES] = run;
}

__global__ void fill_kernel(const int* __restrict__ ei,
                            int* __restrict__ cur, int* __restrict__ srcl)
{
    int e = blockIdx.x * blockDim.x + threadIdx.x;
    if (e >= NEDGE) return;
    int d = ei[NEDGE + e];
    int pos = atomicAdd(cur + d, 1);
    srcl[pos] = ei[e];
}

// ---------------- CSR aggregate ----------------
template<int D>
__global__ void gather_agg_kernel(const int* __restrict__ off,
                                  const int* __restrict__ srcl,
                                  const float* __restrict__ hin,
                                  float* __restrict__ agg)
{
    constexpr int TPN   = (D / 4 < 32) ? D / 4 : 32;
    constexpr int CHUNK = (D / 4) / TPN;
    int gid  = blockIdx.x * blockDim.x + threadIdx.x;
    int node = gid / TPN;
    int sub  = gid % TPN;
    if (node >= NNODES) return;
    int beg = off[node], end = off[node + 1];
    float4 acc[CHUNK];
#pragma unroll
    for (int c = 0; c < CHUNK; c++) acc[c] = make_float4(0.f, 0.f, 0.f, 0.f);
    for (int p = beg; p < end; p++) {
        const float4* r = (const float4*)(hin + (size_t)__ldg(srcl + p) * D);
#pragma unroll
        for (int c = 0; c < CHUNK; c++) {
            float4 v = __ldg(r + sub + c * TPN);
            acc[c].x += v.x; acc[c].y += v.y;
            acc[c].z += v.z; acc[c].w += v.w;
        }
    }
    float4* o = (float4*)(agg + (size_t)node * D);
#pragma unroll
    for (int c = 0; c < CHUNK; c++) o[sub + c * TPN] = acc[c];
}

// ---------------- Fused GIN layer, fragment-order tf32 tensor cores ----------------
// Block = 512 threads = 16 warps; 64 rows x 256 cols. Warp w owns cols [w*16, w*16+16).
// A matrices live in SMEM in mma-fragment order:
//   Af[((k8*4 + mt)*32 + lane)*4 + q], lane = g*4+tg,
//   q: 0=(row g, k tg) 1=(g+8, tg) 2=(g, tg+4) 3=(g+8, tg+4)   -> LDS.128 per frag
// B fragments come straight from global fragment-order weights (L2-hot), LDG.64 each.

template<int K>
__global__ void __launch_bounds__(512)
gin_tc_kernel(const float* __restrict__ hin, const float* __restrict__ agg,
              const float2* __restrict__ Waf, const float* __restrict__ ba,
              const float* __restrict__ gam,  const float* __restrict__ bet,
              const float2* __restrict__ Wbf, const float* __restrict__ bb,
              const float* __restrict__ epsArr, int layer,
              float* __restrict__ hout)
{
    extern __shared__ float smem[];
    float* Pba = smem;                    // 256
    float* Pg  = smem + 256;              // 256
    float* Pb  = smem + 512;              // 256
    float* Af  = smem + 768;              // 16384 (frag A; reused as frag T for phase 2)
    float* Ts  = Af + 16384;              // 64 * 260 row-major (phase-1 result for LN)

    const int t    = threadIdx.x;
    const int lane = t & 31;
    const int warp = t >> 5;
    const int g    = lane >> 2;
    const int tg   = lane & 3;
    const int wb   = warp * 16;
    const int rowBase = blockIdx.x * 64;
    const float ope = 1.0f + epsArr[layer];

    if (t < 256) { Pba[t] = ba[t];  Pg[t] = gam[t];  Pb[t] = bet[t]; }

    // ---- Stage Af: z = tf32((1+eps)*hin + agg), scattered to fragment order ----
    {
        constexpr int K4  = K / 4;
        constexpr int NF4 = 64 * K4 / 512;
#pragma unroll
        for (int j = 0; j < NF4; j++) {
            int i4  = t + 512 * j;
            int row = i4 / K4;
            int c4  = i4 % K4;
            const float* hp = hin + (size_t)(rowBase + row) * K + c4 * 4;
            const float* ap = agg + (size_t)(rowBase + row) * K + c4 * 4;
            float4 hv = *(const float4*)hp;
            float4 av = *(const float4*)ap;
            float zz[4];
            zz[0] = tf32r(fmaf(ope, hv.x, av.x));
            zz[1] = tf32r(fmaf(ope, hv.y, av.y));
            zz[2] = tf32r(fmaf(ope, hv.z, av.z));
            zz[3] = tf32r(fmaf(ope, hv.w, av.w));
            int mt = row >> 4;
            int r  = row & 15;
            int g2 = r & 7;
            int qr = r >> 3;
#pragma unroll
            for (int u = 0; u < 4; u++) {
                int k  = c4 * 4 + u;
                int k8 = k >> 3;
                int tk = k & 3;
                int hi = (k >> 2) & 1;
                Af[(((k8 * 4 + mt) * 32) + g2 * 4 + tk) * 4 + qr + 2 * hi] = zz[u];
            }
        }
    }
    __syncthreads();

    float C[4][2][4];
#pragma unroll
    for (int mt = 0; mt < 4; mt++)
#pragma unroll
        for (int nt = 0; nt < 2; nt++)
#pragma unroll
            for (int q = 0; q < 4; q++) C[mt][nt][q] = 0.0f;

    const int iA = (wb + g) * 4 + tg;       // B-frag index, nt=0
    const int iB = iA + 32;                 // nt=1 (8 cols * 4)

    // ---- Phase 1: Af @ Waf ----
    {
        constexpr int K8 = K / 8;
        float2 b0 = __ldg(Waf + iA);
        float2 b1 = __ldg(Waf + iB);
#pragma unroll
        for (int k8 = 0; k8 < K8; k8++) {
            float2 n0 = b0, n1 = b1;
            if (k8 + 1 < K8) {
                n0 = __ldg(Waf + (k8 + 1) * 1024 + iA);
                n1 = __ldg(Waf + (k8 + 1) * 1024 + iB);
            }
            uint32_t Bf0[2] = { __float_as_uint(b0.x), __float_as_uint(b0.y) };
            uint32_t Bf1[2] = { __float_as_uint(b1.x), __float_as_uint(b1.y) };
#pragma unroll
            for (int mt = 0; mt < 4; mt++) {
                float4 a = *(const float4*)(Af + ((k8 * 4 + mt) * 32 + lane) * 4);
                uint32_t Au[4] = { __float_as_uint(a.x), __float_as_uint(a.y),
                                   __float_as_uint(a.z), __float_as_uint(a.w) };
                mma_tf32(C[mt][0], Au, Bf0);
                mma_tf32(C[mt][1], Au, Bf1);
            }
            b0 = n0; b1 = n1;
        }
    }

    // ---- store C frags to Ts (row-major, padded) ----
#pragma unroll
    for (int mt = 0; mt < 4; mt++)
#pragma unroll
        for (int nt = 0; nt < 2; nt++) {
            int r0  = mt * 16 + g;
            int col = wb + nt * 8 + 2 * tg;
            *(float2*)(Ts +  r0      * 260 + col) = make_float2(C[mt][nt][0], C[mt][nt][1]);
            *(float2*)(Ts + (r0 + 8) * 260 + col) = make_float2(C[mt][nt][2], C[mt][nt][3]);
        }
    __syncthreads();

    // ---- bias + LayerNorm + ReLU; write tf32 result into Af (fragment order) ----
    if (t < 256) {
        int row = t >> 2;
        int q   = t & 3;
        float s = 0.0f, s2 = 0.0f;
#pragma unroll
        for (int c = 0; c < 64; c++) {
            int col = q + c * 4;
            float v = Ts[row * 260 + col] + Pba[col];
            s += v;
            s2 = fmaf(v, v, s2);
        }
        s  += __shfl_xor_sync(0xffffffffu, s, 1);
        s  += __shfl_xor_sync(0xffffffffu, s, 2);
        s2 += __shfl_xor_sync(0xffffffffu, s2, 1);
        s2 += __shfl_xor_sync(0xffffffffu, s2, 2);
        float mean = s * (1.0f / 256.0f);
        float var  = s2 * (1.0f / 256.0f) - mean * mean;
        float inv  = rsqrtf(var + 1e-5f);
        int mt = row >> 4;
        int r  = row & 15;
        int g2 = r & 7;
        int qr = r >> 3;
#pragma unroll
        for (int c = 0; c < 64; c++) {
            int col = q + c * 4;
            float v = (Ts[row * 260 + col] + Pba[col] - mean) * inv;
            v = fmaf(v, Pg[col], Pb[col]);
            v = fmaxf(v, 0.0f);
            int k8 = col >> 3;
            int tk = col & 3;           // == q
            int hi = (col >> 2) & 1;
            Af[(((k8 * 4 + mt) * 32) + g2 * 4 + tk) * 4 + qr + 2 * hi] = tf32r(v);
        }
    }
    __syncthreads();

    // ---- Phase 2: Af(=T) @ Wbf ----
#pragma unroll
    for (int mt = 0; mt < 4; mt++)
#pragma unroll
        for (int nt = 0; nt < 2; nt++)
#pragma unroll
            for (int q = 0; q < 4; q++) C[mt][nt][q] = 0.0f;

    {
        float2 b0 = __ldg(Wbf + iA);
        float2 b1 = __ldg(Wbf + iB);
#pragma unroll
        for (int k8 = 0; k8 < 32; k8++) {
            float2 n0 = b0, n1 = b1;
            if (k8 + 1 < 32) {
                n0 = __ldg(Wbf + (k8 + 1) * 1024 + iA);
                n1 = __ldg(Wbf + (k8 + 1) * 1024 + iB);
            }
            uint32_t Bf0[2] = { __float_as_uint(b0.x), __float_as_uint(b0.y) };
            uint32_t Bf1[2] = { __float_as_uint(b1.x), __float_as_uint(b1.y) };
#pragma unroll
            for (int mt = 0; mt < 4; mt++) {
                float4 a = *(const float4*)(Af + ((k8 * 4 + mt) * 32 + lane) * 4);
                uint32_t Au[4] = { __float_as_uint(a.x), __float_as_uint(a.y),
                                   __float_as_uint(a.z), __float_as_uint(a.w) };
                mma_tf32(C[mt][0], Au, Bf0);
                mma_tf32(C[mt][1], Au, Bf1);
            }
            b0 = n0; b1 = n1;
        }
    }

    // ---- + bb, store to global ----
#pragma unroll
    for (int mt = 0; mt < 4; mt++)
#pragma unroll
        for (int nt = 0; nt < 2; nt++) {
            int r0  = rowBase + mt * 16 + g;
            int col = wb + nt * 8 + 2 * tg;
            float2 bbv = *(const float2*)(bb + col);
            float2 o0 = make_float2(C[mt][nt][0] + bbv.x, C[mt][nt][1] + bbv.y);
            float2 o1 = make_float2(C[mt][nt][2] + bbv.x, C[mt][nt][3] + bbv.y);
            *(float2*)(hout + (size_t) r0      * 256 + col) = o0;
            *(float2*)(hout + (size_t)(r0 + 8) * 256 + col) = o1;
        }
}

// ---------------- Final group reduction ----------------
__global__ void reduce_kernel(const float* __restrict__ h, float* __restrict__ out)
{
    int idx = blockIdx.x * blockDim.x + threadIdx.x;
    if (idx >= NGROUP * 64) return;
    int g  = idx >> 6;
    int c4 = idx & 63;
    const float4* p = (const float4*)h + (size_t)g * 64 * 64 + c4;
    float4 s = make_float4(0.f, 0.f, 0.f, 0.f);
#pragma unroll 8
    for (int j = 0; j < 64; j++) {
        float4 v = p[(size_t)j * 64];
        s.x += v.x; s.y += v.y; s.z += v.z; s.w += v.w;
    }
    ((float4*)out)[idx] = s;
}

// ---------------- Launch ----------------
extern "C" void kernel_launch(void* const* d_in, const int* in_sizes, int n_in,
                              void* d_out, int out_size)
{
    const int*   x     = (const int*)  d_in[0];
    const int*   ei    = (const int*)  d_in[1];
    const float* table = (const float*)d_in[3];
    const float* W0a   = (const float*)d_in[4];
    const float* b0a   = (const float*)d_in[5];
    const float* g0    = (const float*)d_in[6];
    const float* be0   = (const float*)d_in[7];
    const float* W0b   = (const float*)d_in[8];
    const float* b0b   = (const float*)d_in[9];
    const float* Wha   = (const float*)d_in[10];
    const float* bha   = (const float*)d_in[11];
    const float* gh    = (const float*)d_in[12];
    const float* beh   = (const float*)d_in[13];
    const float* Whb   = (const float*)d_in[14];
    const float* bhb   = (const float*)d_in[15];
    const float* eps   = (const float*)d_in[16];

    float *h0, *agg, *hA;
    int *deg, *off, *cur, *srcl;
    float2 *wf;
    cudaGetSymbolAddress((void**)&h0,   g_h0);
    cudaGetSymbolAddress((void**)&agg,  g_agg);
    cudaGetSymbolAddress((void**)&hA,   g_hA);
    cudaGetSymbolAddress((void**)&deg,  g_deg);
    cudaGetSymbolAddress((void**)&off,  g_off);
    cudaGetSymbolAddress((void**)&cur,  g_cur);
    cudaGetSymbolAddress((void**)&srcl, g_srcl);
    cudaGetSymbolAddress((void**)&wf,   g_wf);

    float2* W0af = wf;               // 8  k8 blocks
    float2* W0bf = wf + 8  * 1024;   // 32
    float2* Whaf = wf + 40 * 1024;   // 32
    float2* Whbf = wf + 72 * 1024;   // 32

    const int SMEM_BYTES = (768 + 16384 + 64 * 260) * (int)sizeof(float); // 135168
    cudaFuncSetAttribute((const void*)gin_tc_kernel<64>,
                         cudaFuncAttributeMaxDynamicSharedMemorySize, SMEM_BYTES);
    cudaFuncSetAttribute((const void*)gin_tc_kernel<256>,
                         cudaFuncAttributeMaxDynamicSharedMemorySize, SMEM_BYTES);

    // ---- Weight pre-convert (fragment order, tf32) ----
    wcvt_kernel<<<(8  * 1024 + 255) / 256, 256>>>(W0a, W0af, 8);
    wcvt_kernel<<<(32 * 1024 + 255) / 256, 256>>>(W0b, W0bf, 32);
    wcvt_kernel<<<(32 * 1024 + 255) / 256, 256>>>(Wha, Whaf, 32);
    wcvt_kernel<<<(32 * 1024 + 255) / 256, 256>>>(Whb, Whbf, 32);

    // ---- CSR build ----
    cudaMemsetAsync(deg, 0, (NNODES + 1) * sizeof(int));
    hist_kernel<<<(NEDGE + 255) / 256, 256>>>(ei, deg);
    scan_kernel<<<1, 1024>>>(deg, off, cur);
    fill_kernel<<<(NEDGE + 255) / 256, 256>>>(ei, cur, srcl);

    // ---- Embedding gather ----
    {
        int total = NNODES * (EMBD / 4);
        embed_kernel<<<(total + 255) / 256, 256>>>(x, table, h0);
    }

    // ---- Layer 0 (K = 64) ----
    {
        int total = NNODES * 16;
        gather_agg_kernel<64><<<(total + 255) / 256, 256>>>(off, srcl, h0, agg);
    }
    gin_tc_kernel<64><<<NNODES / 64, 512, SMEM_BYTES>>>(
        h0, agg, W0af, b0a, g0, be0, W0bf, b0b, eps, 0, hA);

    // ---- Layers 1..2 (K = 256) ----
    for (int l = 1; l < 3; l++) {
        int total = NNODES * 32;
        gather_agg_kernel<256><<<(total + 255) / 256, 256>>>(off, srcl, hA, agg);
        gin_tc_kernel<256><<<NNODES / 64, 512, SMEM_BYTES>>>(
            hA, agg, Whaf, bha, gh, beh, Whbf, bhb, eps, l, hA);
    }

    // ---- Final per-graph-node-group sum ----
    {
        int total = NGROUP * 64;
        reduce_kernel<<<(total + 255) / 256, 256>>>(hA, (float*)d_out);
    }
}

// round 7
// speedup vs baseline: 2.9800x; 1.2877x over previous
#include <cuda_runtime.h>
#include <cuda_fp16.h>
#include <cstddef>
#include <cstdint>

// ---------------- Problem constants ----------------
#define NNODES   131072        // B*2*NN
#define HDIM     256
#define EMBD     64
#define NEDGE    1000000
#define NGROUP   2048          // B*2
#define CARD     100

// ---------------- Scratch (no allocs allowed) ----------------
__device__ float g_h0 [NNODES * EMBD];
__device__ float g_z  [NNODES * HDIM];    // fused z = (1+eps)*h + agg
__device__ float g_hA [NNODES * HDIM];
__device__ int   g_deg[NNODES + 1];
__device__ int   g_off[NNODES + 1];
__device__ int   g_cur[NNODES];
__device__ int   g_srcl[NEDGE];
// fp16 fragment-ordered weights: per k16 block: 256 cols x 4 tg, uint2 {lo-pair, hi-pair}
// W0a: 4 blocks | W0b: 16 | Wha: 16 | Whb: 16
__device__ uint2 g_wf16[(4 + 16 + 16 + 16) * 1024];

// ---------------- Helpers ----------------
__device__ __forceinline__ uint32_t h2u(__half2 h) {
    return *reinterpret_cast<uint32_t*>(&h);
}

__device__ __forceinline__ void mma_f16(float (&c)[4], const uint4& a,
                                        uint32_t b0, uint32_t b1) {
    asm volatile(
        "mma.sync.aligned.m16n8k16.row.col.f32.f16.f16.f32 "
        "{%0,%1,%2,%3}, {%4,%5,%6,%7}, {%8,%9}, {%0,%1,%2,%3};"
        : "+f"(c[0]), "+f"(c[1]), "+f"(c[2]), "+f"(c[3])
        : "r"(a.x), "r"(a.y), "r"(a.z), "r"(a.w), "r"(b0), "r"(b1));
}

// ---------------- Weight pre-convert: [K,256] fp32 -> fp16 fragment order ----------------
// out[(k16*256 + col)*4 + tg] = { h2(W[kr+2tg][col], W[kr+2tg+1][col]),
//                                 h2(W[kr+2tg+8][col], W[kr+2tg+9][col]) },  kr = k16*16
__global__ void wcvt16_kernel(const float* __restrict__ W, uint2* __restrict__ out,
                              int k16count)
{
    int idx = blockIdx.x * blockDim.x + threadIdx.x;
    if (idx >= k16count * 1024) return;
    int tg  = idx & 3;
    int col = (idx >> 2) & 255;
    int k16 = idx >> 10;
    int kr  = k16 * 16;
    __half2 lo = __floats2half2_rn(W[(kr + 2 * tg)     * 256 + col],
                                   W[(kr + 2 * tg + 1) * 256 + col]);
    __half2 hi = __floats2half2_rn(W[(kr + 2 * tg + 8) * 256 + col],
                                   W[(kr + 2 * tg + 9) * 256 + col]);
    out[idx] = make_uint2(h2u(lo), h2u(hi));
}

// ---------------- Embedding gather ----------------
__global__ void embed_kernel(const int* __restrict__ x,
                             const float* __restrict__ table,
                             float* __restrict__ h0)
{
    int idx = blockIdx.x * blockDim.x + threadIdx.x;
    if (idx >= NNODES * (EMBD / 4)) return;
    int n  = idx >> 4;
    int c4 = idx & 15;
    int b   = n >> 7;
    int col = n & 127;
    int row = x[(b << 7) + col] + col * CARD;
    ((float4*)h0)[idx] = ((const float4*)table)[row * (EMBD / 4) + c4];
}

// ---------------- CSR build ----------------
__global__ void hist_kernel(const int* __restrict__ ei, int* __restrict__ deg)
{
    int e = blockIdx.x * blockDim.x + threadIdx.x;
    if (e < NEDGE) atomicAdd(deg + ei[NEDGE + e], 1);
}

__global__ void scan_kernel(const int* __restrict__ deg,
                            int* __restrict__ off, int* __restrict__ cur)
{
    __shared__ int ps[1024];
    const int t = threadIdx.x;
    const int base = t * 128;
    int s = 0;
#pragma unroll 8
    for (int i = 0; i < 128; i++) s += deg[base + i];
    ps[t] = s;
    __syncthreads();
    for (int o = 1; o < 1024; o <<= 1) {
        int v = (t >= o) ? ps[t - o] : 0;
        __syncthreads();
        ps[t] += v;
        __syncthreads();
    }
    int run = ps[t] - s;
#pragma unroll 8
    for (int i = 0; i < 128; i++) {
        int d = deg[base + i];
        off[base + i] = run;
        cur[base + i] = run;
        run += d;
    }
    if (t == 1023) off[NNODES] = run;
}

__global__ void fill_kernel(const int* __restrict__ ei,
                            int* __restrict__ cur, int* __restrict__ srcl)
{
    int e = blockIdx.x * blockDim.x + threadIdx.x;
    if (e >= NEDGE) return;
    int d = ei[NEDGE + e];
    int pos = atomicAdd(cur + d, 1);
    srcl[pos] = ei[e];
}

// ---------------- Fused gather + z: z[n] = (1+eps)*h[n] + sum_{s in nbr(n)} h[s] ----------------
template<int D>
__global__ void gather_z_kernel(const int* __restrict__ off,
                                const int* __restrict__ srcl,
                                const float* __restrict__ hin,
                                float* __restrict__ z,
                                const float* __restrict__ epsArr, int layer)
{
    constexpr int TPN   = (D / 4 < 32) ? D / 4 : 32;
    constexpr int CHUNK = (D / 4) / TPN;
    int gid  = blockIdx.x * blockDim.x + threadIdx.x;
    int node = gid / TPN;
    int sub  = gid % TPN;
    if (node >= NNODES) return;
    const float ope = 1.0f + epsArr[layer];
    int beg = off[node], end = off[node + 1];
    float4 acc[CHUNK];
    {
        const float4* r = (const float4*)(hin + (size_t)node * D);
#pragma unroll
        for (int c = 0; c < CHUNK; c++) {
            float4 v = __ldg(r + sub + c * TPN);
            acc[c] = make_float4(ope * v.x, ope * v.y, ope * v.z, ope * v.w);
        }
    }
    for (int p = beg; p < end; p++) {
        const float4* r = (const float4*)(hin + (size_t)__ldg(srcl + p) * D);
#pragma unroll
        for (int c = 0; c < CHUNK; c++) {
            float4 v = __ldg(r + sub + c * TPN);
            acc[c].x += v.x; acc[c].y += v.y;
            acc[c].z += v.z; acc[c].w += v.w;
        }
    }
    float4* o = (float4*)(z + (size_t)node * D);
#pragma unroll
    for (int c = 0; c < CHUNK; c++) o[sub + c * TPN] = acc[c];
}

// ---------------- Fused GIN layer, fp16 m16n8k16 tensor cores ----------------
// Block = 512 threads = 16 warps; 64 rows x 256 cols. Warp w owns cols [w*16, w*16+16).
// A in SMEM in fp16 fragment order, frag group stride 33 (bank-conflict pad):
//   AfU[((k16*4 + mt)*33 + lane)*4 + q], lane = g*4+tg, q packs {row g/g+8} x {k-pair lo/hi}
//   -> one LDS.128 per (k16, mt), conflict-free.
// B fragments direct from global fp16 fragment-order weights: one LDG.64 per (k16, nt).

// SMEM float offsets
#define SPBA   0
#define SPG    256
#define SPB    512
#define AF_OFF 768                 // 8448 uint32 (16 k16 * 4 mt * 33-pad * 4)
#define TS_OFF (768 + 8448)        // 64 * 260 floats
#define GIN_SMEM_F (TS_OFF + 64 * 260)

template<int K>
__global__ void __launch_bounds__(512)
gin_f16_kernel(const float* __restrict__ z,
               const uint2* __restrict__ Waf, const float* __restrict__ ba,
               const float* __restrict__ gam,  const float* __restrict__ bet,
               const uint2* __restrict__ Wbf, const float* __restrict__ bb,
               float* __restrict__ hout)
{
    extern __shared__ float smem[];
    uint32_t* AfU = (uint32_t*)(smem + AF_OFF);
    float*    Ts  = smem + TS_OFF;

    const int t    = threadIdx.x;
    const int lane = t & 31;
    const int warp = t >> 5;
    const int g    = lane >> 2;
    const int tg   = lane & 3;
    const int wb   = warp * 16;
    const int rowBase = blockIdx.x * 64;

    if (t < 256) { smem[SPBA + t] = ba[t]; smem[SPG + t] = gam[t]; smem[SPB + t] = bet[t]; }

    // ---- Stage Af: z -> fp16 fragments ----
    {
        constexpr int K4  = K / 4;
        constexpr int NF4 = 64 * K4 / 512;
#pragma unroll
        for (int j = 0; j < NF4; j++) {
            int i4  = t + 512 * j;
            int row = i4 / K4;
            int c4  = i4 % K4;
            float4 v = *(const float4*)(z + (size_t)(rowBase + row) * K + c4 * 4);
            int mt = row >> 4;
            int r  = row & 15;
            int g2 = r & 7;
            int qr = r >> 3;
            float vv[4] = { v.x, v.y, v.z, v.w };
#pragma unroll
            for (int u = 0; u < 2; u++) {
                int k   = c4 * 4 + 2 * u;
                int kk  = k & 15;
                int k16 = k >> 4;
                int tgs = (kk & 7) >> 1;
                int hi  = kk >> 3;
                __half2 hv = __floats2half2_rn(vv[2 * u], vv[2 * u + 1]);
                AfU[(((k16 * 4 + mt) * 33) + g2 * 4 + tgs) * 4 + qr + 2 * hi] = h2u(hv);
            }
        }
    }
    __syncthreads();

    float C[4][2][4];
#pragma unroll
    for (int mt = 0; mt < 4; mt++)
#pragma unroll
        for (int nt = 0; nt < 2; nt++)
#pragma unroll
            for (int q = 0; q < 4; q++) C[mt][nt][q] = 0.0f;

    const int iA = (wb + g) * 4 + tg;       // B-frag index, nt=0
    const int iB = iA + 32;                 // nt=1

    // ---- Phase 1: Af @ Waf ----
    {
        constexpr int K16 = K / 16;
        uint2 b0 = __ldg(Waf + iA);
        uint2 b1 = __ldg(Waf + iB);
#pragma unroll
        for (int k16 = 0; k16 < K16; k16++) {
            uint2 n0 = b0, n1 = b1;
            if (k16 + 1 < K16) {
                n0 = __ldg(Waf + (k16 + 1) * 1024 + iA);
                n1 = __ldg(Waf + (k16 + 1) * 1024 + iB);
            }
#pragma unroll
            for (int mt = 0; mt < 4; mt++) {
                uint4 a = *(const uint4*)(AfU + ((k16 * 4 + mt) * 33 + lane) * 4);
                mma_f16(C[mt][0], a, b0.x, b0.y);
                mma_f16(C[mt][1], a, b1.x, b1.y);
            }
            b0 = n0; b1 = n1;
        }
    }

    // ---- store C frags to Ts (row-major, padded 260) ----
#pragma unroll
    for (int mt = 0; mt < 4; mt++)
#pragma unroll
        for (int nt = 0; nt < 2; nt++) {
            int r0  = mt * 16 + g;
            int col = wb + nt * 8 + 2 * tg;
            *(float2*)(Ts +  r0      * 260 + col) = make_float2(C[mt][nt][0], C[mt][nt][1]);
            *(float2*)(Ts + (r0 + 8) * 260 + col) = make_float2(C[mt][nt][2], C[mt][nt][3]);
        }
    __syncthreads();

    // ---- bias + LayerNorm + ReLU -> Af (fp16 fragment order) ----
    // Thread (row = t>>2, q = t&3) owns col-pairs p = q + 4c -> cols {2p, 2p+1}.
    if (t < 256) {
        int row = t >> 2;
        int q   = t & 3;
        float s = 0.0f, s2 = 0.0f;
#pragma unroll
        for (int c = 0; c < 32; c++) {
            float2 tv = *(const float2*)(Ts + row * 260 + 2 * q + 8 * c);
            float2 bv = *(const float2*)(smem + SPBA + 2 * q + 8 * c);
            float v0 = tv.x + bv.x, v1 = tv.y + bv.y;
            s += v0 + v1;
            s2 = fmaf(v0, v0, fmaf(v1, v1, s2));
        }
        s  += __shfl_xor_sync(0xffffffffu, s, 1);
        s  += __shfl_xor_sync(0xffffffffu, s, 2);
        s2 += __shfl_xor_sync(0xffffffffu, s2, 1);
        s2 += __shfl_xor_sync(0xffffffffu, s2, 2);
        float mean = s * (1.0f / 256.0f);
        float var  = s2 * (1.0f / 256.0f) - mean * mean;
        float inv  = rsqrtf(var + 1e-5f);
        int mt = row >> 4;
        int r  = row & 15;
        int g2 = r & 7;
        int qr = r >> 3;
#pragma unroll
        for (int c = 0; c < 32; c++) {
            float2 tv = *(const float2*)(Ts + row * 260 + 2 * q + 8 * c);
            float2 bv = *(const float2*)(smem + SPBA + 2 * q + 8 * c);
            float2 gv = *(const float2*)(smem + SPG  + 2 * q + 8 * c);
            float2 ev = *(const float2*)(smem + SPB  + 2 * q + 8 * c);
            float v0 = fmaf((tv.x + bv.x - mean) * inv, gv.x, ev.x);
            float v1 = fmaf((tv.y + bv.y - mean) * inv, gv.y, ev.y);
            v0 = fmaxf(v0, 0.0f);
            v1 = fmaxf(v1, 0.0f);
            int p   = q + 4 * c;
            int k16 = p >> 3;
            int hi  = c & 1;
            __half2 hv = __floats2half2_rn(v0, v1);
            AfU[(((k16 * 4 + mt) * 33) + g2 * 4 + q) * 4 + qr + 2 * hi] = h2u(hv);
        }
    }
    __syncthreads();

    // ---- Phase 2: Af(=T) @ Wbf ----
#pragma unroll
    for (int mt = 0; mt < 4; mt++)
#pragma unroll
        for (int nt = 0; nt < 2; nt++)
#pragma unroll
            for (int q = 0; q < 4; q++) C[mt][nt][q] = 0.0f;

    {
        uint2 b0 = __ldg(Wbf + iA);
        uint2 b1 = __ldg(Wbf + iB);
#pragma unroll
        for (int k16 = 0; k16 < 16; k16++) {
            uint2 n0 = b0, n1 = b1;
            if (k16 + 1 < 16) {
                n0 = __ldg(Wbf + (k16 + 1) * 1024 + iA);
                n1 = __ldg(Wbf + (k16 + 1) * 1024 + iB);
            }
#pragma unroll
            for (int mt = 0; mt < 4; mt++) {
                uint4 a = *(const uint4*)(AfU + ((k16 * 4 + mt) * 33 + lane) * 4);
                mma_f16(C[mt][0], a, b0.x, b0.y);
                mma_f16(C[mt][1], a, b1.x, b1.y);
            }
            b0 = n0; b1 = n1;
        }
    }

    // ---- + bb, store to global ----
#pragma unroll
    for (int mt = 0; mt < 4; mt++)
#pragma unroll
        for (int nt = 0; nt < 2; nt++) {
            int r0  = rowBase + mt * 16 + g;
            int col = wb + nt * 8 + 2 * tg;
            float2 bbv = *(const float2*)(bb + col);
            float2 o0 = make_float2(C[mt][nt][0] + bbv.x, C[mt][nt][1] + bbv.y);
            float2 o1 = make_float2(C[mt][nt][2] + bbv.x, C[mt][nt][3] + bbv.y);
            *(float2*)(hout + (size_t) r0      * 256 + col) = o0;
            *(float2*)(hout + (size_t)(r0 + 8) * 256 + col) = o1;
        }
}

// ---------------- Final group reduction ----------------
__global__ void reduce_kernel(const float* __restrict__ h, float* __restrict__ out)
{
    int idx = blockIdx.x * blockDim.x + threadIdx.x;
    if (idx >= NGROUP * 64) return;
    int g  = idx >> 6;
    int c4 = idx & 63;
    const float4* p = (const float4*)h + (size_t)g * 64 * 64 + c4;
    float4 s = make_float4(0.f, 0.f, 0.f, 0.f);
#pragma unroll 8
    for (int j = 0; j < 64; j++) {
        float4 v = p[(size_t)j * 64];
        s.x += v.x; s.y += v.y; s.z += v.z; s.w += v.w;
    }
    ((float4*)out)[idx] = s;
}

// ---------------- Launch ----------------
extern "C" void kernel_launch(void* const* d_in, const int* in_sizes, int n_in,
                              void* d_out, int out_size)
{
    const int*   x     = (const int*)  d_in[0];
    const int*   ei    = (const int*)  d_in[1];
    const float* table = (const float*)d_in[3];
    const float* W0a   = (const float*)d_in[4];
    const float* b0a   = (const float*)d_in[5];
    const float* g0    = (const float*)d_in[6];
    const float* be0   = (const float*)d_in[7];
    const float* W0b   = (const float*)d_in[8];
    const float* b0b   = (const float*)d_in[9];
    const float* Wha   = (const float*)d_in[10];
    const float* bha   = (const float*)d_in[11];
    const float* gh    = (const float*)d_in[12];
    const float* beh   = (const float*)d_in[13];
    const float* Whb   = (const float*)d_in[14];
    const float* bhb   = (const float*)d_in[15];
    const float* eps   = (const float*)d_in[16];

    float *h0, *z, *hA;
    int *deg, *off, *cur, *srcl;
    uint2 *wf;
    cudaGetSymbolAddress((void**)&h0,   g_h0);
    cudaGetSymbolAddress((void**)&z,    g_z);
    cudaGetSymbolAddress((void**)&hA,   g_hA);
    cudaGetSymbolAddress((void**)&deg,  g_deg);
    cudaGetSymbolAddress((void**)&off,  g_off);
    cudaGetSymbolAddress((void**)&cur,  g_cur);
    cudaGetSymbolAddress((void**)&srcl, g_srcl);
    cudaGetSymbolAddress((void**)&wf,   g_wf16);

    uint2* W0af = wf;               // 4 k16 blocks
    uint2* W0bf = wf + 4  * 1024;   // 16
    uint2* Whaf = wf + 20 * 1024;   // 16
    uint2* Whbf = wf + 36 * 1024;   // 16

    const int SMEM_BYTES = GIN_SMEM_F * (int)sizeof(float);
    cudaFuncSetAttribute((const void*)gin_f16_kernel<64>,
                         cudaFuncAttributeMaxDynamicSharedMemorySize, SMEM_BYTES);
    cudaFuncSetAttribute((const void*)gin_f16_kernel<256>,
                         cudaFuncAttributeMaxDynamicSharedMemorySize, SMEM_BYTES);

    // ---- Weight pre-convert (fp16 fragment order) ----
    wcvt16_kernel<<<(4  * 1024 + 255) / 256, 256>>>(W0a, W0af, 4);
    wcvt16_kernel<<<(16 * 1024 + 255) / 256, 256>>>(W0b, W0bf, 16);
    wcvt16_kernel<<<(16 * 1024 + 255) / 256, 256>>>(Wha, Whaf, 16);
    wcvt16_kernel<<<(16 * 1024 + 255) / 256, 256>>>(Whb, Whbf, 16);

    // ---- CSR build ----
    cudaMemsetAsync(deg, 0, (NNODES + 1) * sizeof(int));
    hist_kernel<<<(NEDGE + 255) / 256, 256>>>(ei, deg);
    scan_kernel<<<1, 1024>>>(deg, off, cur);
    fill_kernel<<<(NEDGE + 255) / 256, 256>>>(ei, cur, srcl);

    // ---- Embedding gather ----
    {
        int total = NNODES * (EMBD / 4);
        embed_kernel<<<(total + 255) / 256, 256>>>(x, table, h0);
    }

    // ---- Layer 0 (K = 64) ----
    {
        int total = NNODES * 16;
        gather_z_kernel<64><<<(total + 255) / 256, 256>>>(off, srcl, h0, z, eps, 0);
    }
    gin_f16_kernel<64><<<NNODES / 64, 512, SMEM_BYTES>>>(
        z, W0af, b0a, g0, be0, W0bf, b0b, hA);

    // ---- Layers 1..2 (K = 256) ----
    for (int l = 1; l < 3; l++) {
        int total = NNODES * 32;
        gather_z_kernel<256><<<(total + 255) / 256, 256>>>(off, srcl, hA, z, eps, l);
        gin_f16_kernel<256><<<NNODES / 64, 512, SMEM_BYTES>>>(
            z, Whaf, bha, gh, beh, Whbf, bhb, hA);
    }

    // ---- Final per-graph-node-group sum ----
    {
        int total = NGROUP * 64;
        reduce_kernel<<<(total + 255) / 256, 256>>>(hA, (float*)d_out);
    }
}

// round 8
// speedup vs baseline: 3.4701x; 1.1645x over previous
#include <cuda_runtime.h>
#include <cuda_fp16.h>
#include <cstddef>
#include <cstdint>

// ---------------- Problem constants ----------------
#define NNODES   131072        // B*2*NN
#define HDIM     256
#define EMBD     64
#define NEDGE    1000000
#define NGROUP   2048          // B*2
#define CARD     100

// ---------------- Scratch (no allocs allowed) ----------------
__device__ __align__(16) __half g_h0 [NNODES * EMBD];
__device__ __align__(16) __half g_z  [NNODES * HDIM];  // fused z = (1+eps)*h + agg
__device__ __align__(16) __half g_hA [NNODES * HDIM];  // node features (fp16)
__device__ int   g_deg[NNODES + 1];
__device__ int   g_off[NNODES + 1];
__device__ int   g_cur[NNODES];
__device__ int   g_srcl[NEDGE];
// fp16 fragment-ordered weights: per k16 block: 256 cols x 4 tg, uint2 {lo-pair, hi-pair}
__device__ uint2 g_wf16[(4 + 16 + 16 + 16) * 1024];

// ---------------- Helpers ----------------
__device__ __forceinline__ uint32_t h2u(__half2 h) {
    return *reinterpret_cast<uint32_t*>(&h);
}
__device__ __forceinline__ float2 u2f2(uint32_t u) {
    return __half22float2(*reinterpret_cast<__half2*>(&u));
}

__device__ __forceinline__ void mma_f16(float (&c)[4], const uint4& a,
                                        uint32_t b0, uint32_t b1) {
    asm volatile(
        "mma.sync.aligned.m16n8k16.row.col.f32.f16.f16.f32 "
        "{%0,%1,%2,%3}, {%4,%5,%6,%7}, {%8,%9}, {%0,%1,%2,%3};"
        : "+f"(c[0]), "+f"(c[1]), "+f"(c[2]), "+f"(c[3])
        : "r"(a.x), "r"(a.y), "r"(a.z), "r"(a.w), "r"(b0), "r"(b1));
}

// ---------------- Weight pre-convert: [K,256] fp32 -> fp16 fragment order ----------------
__global__ void wcvt16_kernel(const float* __restrict__ W, uint2* __restrict__ out,
                              int k16count)
{
    int idx = blockIdx.x * blockDim.x + threadIdx.x;
    if (idx >= k16count * 1024) return;
    int tg  = idx & 3;
    int col = (idx >> 2) & 255;
    int k16 = idx >> 10;
    int kr  = k16 * 16;
    __half2 lo = __floats2half2_rn(W[(kr + 2 * tg)     * 256 + col],
                                   W[(kr + 2 * tg + 1) * 256 + col]);
    __half2 hi = __floats2half2_rn(W[(kr + 2 * tg + 8) * 256 + col],
                                   W[(kr + 2 * tg + 9) * 256 + col]);
    out[idx] = make_uint2(h2u(lo), h2u(hi));
}

// ---------------- Embedding gather (fp32 table -> fp16 h0) ----------------
__global__ void embed_kernel(const int* __restrict__ x,
                             const float* __restrict__ table,
                             __half* __restrict__ h0)
{
    int idx = blockIdx.x * blockDim.x + threadIdx.x;   // NNODES * 8 (8 halves each)
    if (idx >= NNODES * 8) return;
    int n  = idx >> 3;
    int c8 = idx & 7;
    int b   = n >> 7;
    int col = n & 127;
    int row = x[(b << 7) + col] + col * CARD;
    const float4* src = (const float4*)(table + (size_t)row * 64) + c8 * 2;
    float4 a = __ldg(src);
    float4 c = __ldg(src + 1);
    uint4 o;
    o.x = h2u(__floats2half2_rn(a.x, a.y));
    o.y = h2u(__floats2half2_rn(a.z, a.w));
    o.z = h2u(__floats2half2_rn(c.x, c.y));
    o.w = h2u(__floats2half2_rn(c.z, c.w));
    ((uint4*)h0)[idx] = o;
}

// ---------------- CSR build ----------------
__global__ void hist_kernel(const int* __restrict__ ei, int* __restrict__ deg)
{
    int e = blockIdx.x * blockDim.x + threadIdx.x;
    if (e < NEDGE) atomicAdd(deg + ei[NEDGE + e], 1);
}

__global__ void scan_kernel(const int* __restrict__ deg,
                            int* __restrict__ off, int* __restrict__ cur)
{
    __shared__ int ps[1024];
    const int t = threadIdx.x;
    const int base = t * 128;
    int s = 0;
#pragma unroll 8
    for (int i = 0; i < 128; i++) s += deg[base + i];
    ps[t] = s;
    __syncthreads();
    for (int o = 1; o < 1024; o <<= 1) {
        int v = (t >= o) ? ps[t - o] : 0;
        __syncthreads();
        ps[t] += v;
        __syncthreads();
    }
    int run = ps[t] - s;
#pragma unroll 8
    for (int i = 0; i < 128; i++) {
        int d = deg[base + i];
        off[base + i] = run;
        cur[base + i] = run;
        run += d;
    }
    if (t == 1023) off[NNODES] = run;
}

__global__ void fill_kernel(const int* __restrict__ ei,
                            int* __restrict__ cur, int* __restrict__ srcl)
{
    int e = blockIdx.x * blockDim.x + threadIdx.x;
    if (e >= NEDGE) return;
    int d = ei[NEDGE + e];
    int pos = atomicAdd(cur + d, 1);
    srcl[pos] = ei[e];
}

// ---------------- Fused gather + z (fp16 in/out, fp32 accumulate) ----------------
// z[n] = (1+eps)*h[n] + sum_{s in nbr(n)} h[s]
template<int D>   // halves per row
__global__ void gather_z_kernel(const int* __restrict__ off,
                                const int* __restrict__ srcl,
                                const __half* __restrict__ hin,
                                __half* __restrict__ z,
                                const float* __restrict__ epsArr, int layer)
{
    constexpr int TPN = D / 8;      // uint4 (8 halves) per thread
    int gid  = blockIdx.x * blockDim.x + threadIdx.x;
    int node = gid / TPN;
    int sub  = gid % TPN;
    if (node >= NNODES) return;
    const float ope = 1.0f + epsArr[layer];
    int beg = off[node], end = off[node + 1];
    const uint4* hu = (const uint4*)hin;
    float a[8];
    {
        uint4 v = __ldg(hu + (size_t)node * TPN + sub);
        float2 f0 = u2f2(v.x), f1 = u2f2(v.y), f2 = u2f2(v.z), f3 = u2f2(v.w);
        a[0] = ope * f0.x; a[1] = ope * f0.y;
        a[2] = ope * f1.x; a[3] = ope * f1.y;
        a[4] = ope * f2.x; a[5] = ope * f2.y;
        a[6] = ope * f3.x; a[7] = ope * f3.y;
    }
    for (int p = beg; p < end; p++) {
        uint4 v = __ldg(hu + (size_t)__ldg(srcl + p) * TPN + sub);
        float2 f0 = u2f2(v.x), f1 = u2f2(v.y), f2 = u2f2(v.z), f3 = u2f2(v.w);
        a[0] += f0.x; a[1] += f0.y;
        a[2] += f1.x; a[3] += f1.y;
        a[4] += f2.x; a[5] += f2.y;
        a[6] += f3.x; a[7] += f3.y;
    }
    uint4 o;
    o.x = h2u(__floats2half2_rn(a[0], a[1]));
    o.y = h2u(__floats2half2_rn(a[2], a[3]));
    o.z = h2u(__floats2half2_rn(a[4], a[5]));
    o.w = h2u(__floats2half2_rn(a[6], a[7]));
    ((uint4*)z)[(size_t)node * TPN + sub] = o;
}

// ---------------- Fused GIN layer, fp16 m16n8k16 tensor cores ----------------
// Block = 512 threads = 16 warps; 64 rows x 256 cols. Warp w owns cols [w*16, w*16+16).
// z arrives fp16-packed in exactly the half2 k-pair granularity the a-fragments use.

// SMEM float offsets
#define SPBA   0
#define SPG    256
#define SPB    512
#define AF_OFF 768                 // 8448 uint32 (16 k16 * 4 mt * 33-pad * 4)
#define TS_OFF (768 + 8448)        // 64 * 260 floats
#define GIN_SMEM_F (TS_OFF + 64 * 260)

template<int K>
__global__ void __launch_bounds__(512)
gin_f16_kernel(const __half* __restrict__ z,
               const uint2* __restrict__ Waf, const float* __restrict__ ba,
               const float* __restrict__ gam,  const float* __restrict__ bet,
               const uint2* __restrict__ Wbf, const float* __restrict__ bb,
               __half* __restrict__ hout)
{
    extern __shared__ float smem[];
    uint32_t* AfU = (uint32_t*)(smem + AF_OFF);
    float*    Ts  = smem + TS_OFF;

    const int t    = threadIdx.x;
    const int lane = t & 31;
    const int warp = t >> 5;
    const int g    = lane >> 2;
    const int tg   = lane & 3;
    const int wb   = warp * 16;
    const int rowBase = blockIdx.x * 64;

    if (t < 256) { smem[SPBA + t] = ba[t]; smem[SPG + t] = gam[t]; smem[SPB + t] = bet[t]; }

    // ---- Stage Af: fp16 z -> fragment order (pure shuffle, no convert) ----
    {
        constexpr int U4R = K / 8;              // uint4 per row
        constexpr int NIT = 64 * U4R / 512;     // 1 (K=64) or 4 (K=256)
        const uint4* zU = (const uint4*)z;
#pragma unroll
        for (int j = 0; j < NIT; j++) {
            int i4  = t + 512 * j;
            int row = i4 / U4R;
            int pos = i4 % U4R;
            uint4 v = zU[(size_t)(rowBase + row) * U4R + pos];
            int mt = row >> 4;
            int r  = row & 15;
            int g2 = r & 7;
            int qr = r >> 3;
            int k16 = pos >> 1;
            int hi  = pos & 1;
            uint32_t* base = AfU + (((k16 * 4 + mt) * 33) + g2 * 4) * 4 + qr + 2 * hi;
            base[0]  = v.x;   // tgs 0
            base[4]  = v.y;   // tgs 1
            base[8]  = v.z;   // tgs 2
            base[12] = v.w;   // tgs 3
        }
    }
    __syncthreads();

    float C[4][2][4];
#pragma unroll
    for (int mt = 0; mt < 4; mt++)
#pragma unroll
        for (int nt = 0; nt < 2; nt++)
#pragma unroll
            for (int q = 0; q < 4; q++) C[mt][nt][q] = 0.0f;

    const int iA = (wb + g) * 4 + tg;
    const int iB = iA + 32;

    // ---- Phase 1: Af @ Waf ----
    {
        constexpr int K16 = K / 16;
        uint2 b0 = __ldg(Waf + iA);
        uint2 b1 = __ldg(Waf + iB);
#pragma unroll
        for (int k16 = 0; k16 < K16; k16++) {
            uint2 n0 = b0, n1 = b1;
            if (k16 + 1 < K16) {
                n0 = __ldg(Waf + (k16 + 1) * 1024 + iA);
                n1 = __ldg(Waf + (k16 + 1) * 1024 + iB);
            }
#pragma unroll
            for (int mt = 0; mt < 4; mt++) {
                uint4 a = *(const uint4*)(AfU + ((k16 * 4 + mt) * 33 + lane) * 4);
                mma_f16(C[mt][0], a, b0.x, b0.y);
                mma_f16(C[mt][1], a, b1.x, b1.y);
            }
            b0 = n0; b1 = n1;
        }
    }

    // ---- store C frags to Ts (row-major, padded 260) ----
#pragma unroll
    for (int mt = 0; mt < 4; mt++)
#pragma unroll
        for (int nt = 0; nt < 2; nt++) {
            int r0  = mt * 16 + g;
            int col = wb + nt * 8 + 2 * tg;
            *(float2*)(Ts +  r0      * 260 + col) = make_float2(C[mt][nt][0], C[mt][nt][1]);
            *(float2*)(Ts + (r0 + 8) * 260 + col) = make_float2(C[mt][nt][2], C[mt][nt][3]);
        }
    __syncthreads();

    // ---- bias + LayerNorm + ReLU -> Af (fp16 fragment order) ----
    if (t < 256) {
        int row = t >> 2;
        int q   = t & 3;
        float s = 0.0f, s2 = 0.0f;
#pragma unroll
        for (int c = 0; c < 32; c++) {
            float2 tv = *(const float2*)(Ts + row * 260 + 2 * q + 8 * c);
            float2 bv = *(const float2*)(smem + SPBA + 2 * q + 8 * c);
            float v0 = tv.x + bv.x, v1 = tv.y + bv.y;
            s += v0 + v1;
            s2 = fmaf(v0, v0, fmaf(v1, v1, s2));
        }
        s  += __shfl_xor_sync(0xffffffffu, s, 1);
        s  += __shfl_xor_sync(0xffffffffu, s, 2);
        s2 += __shfl_xor_sync(0xffffffffu, s2, 1);
        s2 += __shfl_xor_sync(0xffffffffu, s2, 2);
        float mean = s * (1.0f / 256.0f);
        float var  = s2 * (1.0f / 256.0f) - mean * mean;
        float inv  = rsqrtf(var + 1e-5f);
        int mt = row >> 4;
        int r  = row & 15;
        int g2 = r & 7;
        int qr = r >> 3;
#pragma unroll
        for (int c = 0; c < 32; c++) {
            float2 tv = *(const float2*)(Ts + row * 260 + 2 * q + 8 * c);
            float2 bv = *(const float2*)(smem + SPBA + 2 * q + 8 * c);
            float2 gv = *(const float2*)(smem + SPG  + 2 * q + 8 * c);
            float2 ev = *(const float2*)(smem + SPB  + 2 * q + 8 * c);
            float v0 = fmaf((tv.x + bv.x - mean) * inv, gv.x, ev.x);
            float v1 = fmaf((tv.y + bv.y - mean) * inv, gv.y, ev.y);
            v0 = fmaxf(v0, 0.0f);
            v1 = fmaxf(v1, 0.0f);
            int p   = q + 4 * c;
            int k16 = p >> 3;
            int hi  = c & 1;
            __half2 hv = __floats2half2_rn(v0, v1);
            AfU[(((k16 * 4 + mt) * 33) + g2 * 4 + q) * 4 + qr + 2 * hi] = h2u(hv);
        }
    }
    __syncthreads();

    // ---- Phase 2: Af(=T) @ Wbf ----
#pragma unroll
    for (int mt = 0; mt < 4; mt++)
#pragma unroll
        for (int nt = 0; nt < 2; nt++)
#pragma unroll
            for (int q = 0; q < 4; q++) C[mt][nt][q] = 0.0f;

    {
        uint2 b0 = __ldg(Wbf + iA);
        uint2 b1 = __ldg(Wbf + iB);
#pragma unroll
        for (int k16 = 0; k16 < 16; k16++) {
            uint2 n0 = b0, n1 = b1;
            if (k16 + 1 < 16) {
                n0 = __ldg(Wbf + (k16 + 1) * 1024 + iA);
                n1 = __ldg(Wbf + (k16 + 1) * 1024 + iB);
            }
#pragma unroll
            for (int mt = 0; mt < 4; mt++) {
                uint4 a = *(const uint4*)(AfU + ((k16 * 4 + mt) * 33 + lane) * 4);
                mma_f16(C[mt][0], a, b0.x, b0.y);
                mma_f16(C[mt][1], a, b1.x, b1.y);
            }
            b0 = n0; b1 = n1;
        }
    }

    // ---- + bb, store fp16 to global ----
    {
        uint32_t* ho = (uint32_t*)hout;
#pragma unroll
        for (int mt = 0; mt < 4; mt++)
#pragma unroll
            for (int nt = 0; nt < 2; nt++) {
                int r0  = rowBase + mt * 16 + g;
                int col = wb + nt * 8 + 2 * tg;
                float2 bbv = *(const float2*)(bb + col);
                __half2 o0 = __floats2half2_rn(C[mt][nt][0] + bbv.x, C[mt][nt][1] + bbv.y);
                __half2 o1 = __floats2half2_rn(C[mt][nt][2] + bbv.x, C[mt][nt][3] + bbv.y);
                ho[(size_t) r0      * 128 + (col >> 1)] = h2u(o0);
                ho[(size_t)(r0 + 8) * 128 + (col >> 1)] = h2u(o1);
            }
    }
}

// ---------------- Final group reduction (fp16 in, fp32 out) ----------------
__global__ void reduce_kernel(const __half* __restrict__ h, float* __restrict__ out)
{
    int idx = blockIdx.x * blockDim.x + threadIdx.x;   // NGROUP * 32 (8 halves each)
    if (idx >= NGROUP * 32) return;
    int g  = idx >> 5;
    int c8 = idx & 31;
    const uint4* p = (const uint4*)h + (size_t)g * 64 * 32 + c8;
    float a[8] = {0, 0, 0, 0, 0, 0, 0, 0};
#pragma unroll 8
    for (int j = 0; j < 64; j++) {
        uint4 v = p[(size_t)j * 32];
        float2 f0 = u2f2(v.x), f1 = u2f2(v.y), f2 = u2f2(v.z), f3 = u2f2(v.w);
        a[0] += f0.x; a[1] += f0.y; a[2] += f1.x; a[3] += f1.y;
        a[4] += f2.x; a[5] += f2.y; a[6] += f3.x; a[7] += f3.y;
    }
    float4* o = (float4*)(out + (size_t)g * 256 + c8 * 8);
    o[0] = make_float4(a[0], a[1], a[2], a[3]);
    o[1] = make_float4(a[4], a[5], a[6], a[7]);
}

// ---------------- Launch ----------------
extern "C" void kernel_launch(void* const* d_in, const int* in_sizes, int n_in,
                              void* d_out, int out_size)
{
    const int*   x     = (const int*)  d_in[0];
    const int*   ei    = (const int*)  d_in[1];
    const float* table = (const float*)d_in[3];
    const float* W0a   = (const float*)d_in[4];
    const float* b0a   = (const float*)d_in[5];
    const float* g0    = (const float*)d_in[6];
    const float* be0   = (const float*)d_in[7];
    const float* W0b   = (const float*)d_in[8];
    const float* b0b   = (const float*)d_in[9];
    const float* Wha   = (const float*)d_in[10];
    const float* bha   = (const float*)d_in[11];
    const float* gh    = (const float*)d_in[12];
    const float* beh   = (const float*)d_in[13];
    const float* Whb   = (const float*)d_in[14];
    const float* bhb   = (const float*)d_in[15];
    const float* eps   = (const float*)d_in[16];

    __half *h0, *z, *hA;
    int *deg, *off, *cur, *srcl;
    uint2 *wf;
    cudaGetSymbolAddress((void**)&h0,   g_h0);
    cudaGetSymbolAddress((void**)&z,    g_z);
    cudaGetSymbolAddress((void**)&hA,   g_hA);
    cudaGetSymbolAddress((void**)&deg,  g_deg);
    cudaGetSymbolAddress((void**)&off,  g_off);
    cudaGetSymbolAddress((void**)&cur,  g_cur);
    cudaGetSymbolAddress((void**)&srcl, g_srcl);
    cudaGetSymbolAddress((void**)&wf,   g_wf16);

    uint2* W0af = wf;               // 4 k16 blocks
    uint2* W0bf = wf + 4  * 1024;   // 16
    uint2* Whaf = wf + 20 * 1024;   // 16
    uint2* Whbf = wf + 36 * 1024;   // 16

    const int SMEM_BYTES = GIN_SMEM_F * (int)sizeof(float);
    cudaFuncSetAttribute((const void*)gin_f16_kernel<64>,
                         cudaFuncAttributeMaxDynamicSharedMemorySize, SMEM_BYTES);
    cudaFuncSetAttribute((const void*)gin_f16_kernel<256>,
                         cudaFuncAttributeMaxDynamicSharedMemorySize, SMEM_BYTES);

    // ---- Weight pre-convert (fp16 fragment order) ----
    wcvt16_kernel<<<(4  * 1024 + 255) / 256, 256>>>(W0a, W0af, 4);
    wcvt16_kernel<<<(16 * 1024 + 255) / 256, 256>>>(W0b, W0bf, 16);
    wcvt16_kernel<<<(16 * 1024 + 255) / 256, 256>>>(Wha, Whaf, 16);
    wcvt16_kernel<<<(16 * 1024 + 255) / 256, 256>>>(Whb, Whbf, 16);

    // ---- CSR build ----
    cudaMemsetAsync(deg, 0, (NNODES + 1) * sizeof(int));
    hist_kernel<<<(NEDGE + 255) / 256, 256>>>(ei, deg);
    scan_kernel<<<1, 1024>>>(deg, off, cur);
    fill_kernel<<<(NEDGE + 255) / 256, 256>>>(ei, cur, srcl);

    // ---- Embedding gather ----
    embed_kernel<<<(NNODES * 8 + 255) / 256, 256>>>(x, table, h0);

    // ---- Layer 0 (K = 64) ----
    gather_z_kernel<64><<<(NNODES * 8 + 255) / 256, 256>>>(off, srcl, h0, z, eps, 0);
    gin_f16_kernel<64><<<NNODES / 64, 512, SMEM_BYTES>>>(
        z, W0af, b0a, g0, be0, W0bf, b0b, hA);

    // ---- Layers 1..2 (K = 256) ----
    for (int l = 1; l < 3; l++) {
        gather_z_kernel<256><<<(NNODES * 32 + 255) / 256, 256>>>(off, srcl, hA, z, eps, l);
        gin_f16_kernel<256><<<NNODES / 64, 512, SMEM_BYTES>>>(
            z, Whaf, bha, gh, beh, Whbf, bhb, hA);
    }

    // ---- Final per-graph-node-group sum ----
    reduce_kernel<<<(NGROUP * 32 + 255) / 256, 256>>>(hA, (float*)d_out);
}